// round 9
// baseline (speedup 1.0000x reference)
#include <cuda_runtime.h>
#include <stdint.h>

#define TT 32
#define NB 4
#define FRAMES (TT*NB)

#define C0 128
#define H0 16
#define W0 16
#define C1 64
#define H1 31
#define W1 31
#define C2 32
#define H2 61
#define W2 61
#define C3 2
#define H3 121
#define W3 121

#define P0 (H0*W0)     // 256
#define P1 (H1*W1)     // 961
#define P2 (H2*W2)     // 3721
#define P3 (H3*W3)     // 14641

typedef unsigned long long u64;

// ---- device scratch ----
__device__ uint8_t g_cnt0[FRAMES*P0];
__device__ uint8_t g_lst0[FRAMES*P0*128];
__device__ float   g_w1r[9*C0*C1];                    // [tap][ci][co], x2 scaled
__device__ float   g_w2r[9*C1*C2];
__device__ float   g_w3r[9*C2*C3];
__device__ float   g_z1[(size_t)FRAMES*P1*C1];
__device__ uint8_t g_cnt1[FRAMES*P1];
__device__ uint8_t g_lst1[FRAMES*P1*64];
__device__ float   g_z2[(size_t)FRAMES*P2*C2];
__device__ uint8_t g_cnt2[FRAMES*P2];
__device__ uint8_t g_lst2[FRAMES*P2*32];
__device__ int     g_cnt[3];

#define ADD2(A, W) asm("add.rn.f32x2 %0, %0, %1;" : "+l"(A) : "l"(W))

// ---- merged prep: blocks [0,128) build layer-0 lists (warp per (n,pix), no barriers);
//      blocks >= 128 rearrange weights and zero counters ----
__global__ void k_prep(const float* __restrict__ x, const float* __restrict__ w1,
                       const float* __restrict__ w2, const float* __restrict__ w3) {
    if (blockIdx.x >= 128) {
        int idx = (blockIdx.x - 128)*256 + threadIdx.x;
        if (idx < 3) g_cnt[idx] = 0;
        if (idx < 9*C0*C1) {
            int co = idx & 63;
            int ci = (idx >> 6) & 127;
            int tap = idx >> 13;
            g_w1r[idx] = 2.0f * w1[(ci*C1 + co)*9 + tap];
        } else if (idx < 9*C0*C1 + 9*C1*C2) {
            int i = idx - 9*C0*C1;
            int co = i & 31;
            int ci = (i >> 5) & 63;
            int tap = i >> 11;
            g_w2r[i] = 2.0f * w2[(ci*C2 + co)*9 + tap];
        } else if (idx < 9*C0*C1 + 9*C1*C2 + 9*C2*C3) {
            int i = idx - (9*C0*C1 + 9*C1*C2);
            int co = i & 1;
            int ci = (i >> 1) & 31;
            int tap = i >> 6;
            g_w3r[i] = 2.0f * w3[(ci*C3 + co)*9 + tap];
        }
        return;
    }
    const int lane = threadIdx.x & 31;
    const int gw = blockIdx.x*8 + (threadIdx.x >> 5);   // 1024 warps = NB*P0 exact
    const int pix = gw % P0;
    const int n   = gw / P0;
    const uint32_t ltmask = (1u << lane) - 1u;
    uint32_t tmask[4];
    #pragma unroll
    for (int w = 0; w < 4; w++) {
        const float4* xp = (const float4*)(x + (((size_t)n*C0 + w*32 + lane)*P0 + pix)*TT);
        uint32_t m = 0;
        #pragma unroll
        for (int q = 0; q < 8; q++) {
            float4 vv = xp[q];
            m |= (vv.x >= 0.5f ? 1u : 0u) << (4*q);
            m |= (vv.y >= 0.5f ? 1u : 0u) << (4*q+1);
            m |= (vv.z >= 0.5f ? 1u : 0u) << (4*q+2);
            m |= (vv.w >= 0.5f ? 1u : 0u) << (4*q+3);
        }
        tmask[w] = m;
    }
    #pragma unroll 1
    for (int t = 0; t < TT; t++) {
        const int p = (t*NB + n)*P0 + pix;
        uint8_t* lb = g_lst0 + p*128;
        int off = 0;
        #pragma unroll
        for (int w = 0; w < 4; w++) {
            bool s = (tmask[w] >> t) & 1u;
            uint32_t bal = __ballot_sync(0xffffffffu, s);
            if (s) lb[off + __popc(bal & ltmask)] = (uint8_t)(w*32 + lane);
            off += __popc(bal);
        }
        if (lane == 0) g_cnt0[p] = (uint8_t)off;
    }
}

#define EV1(I) { u64 w_ = wb[(I)*32]; ADD2(acc, w_); }
#define EV2(I) { acc += wb[(I)*32]; }

// ==== layer 1 conv body (merged list, 64 couts packed in f32x2) ====
template<int PH, int PW>
__device__ __forceinline__ void conv1body(float* sW, int firstBlk, int nblk) {
    constexpr int NKH = PH ? 2 : 1;
    constexpr int NKW = PW ? 2 : 1;
    constexpr int NT = NKH*NKW;
    for (int i = threadIdx.x; i < NT*C0*C1; i += 1024) {
        int ti = i >> 13;
        int r  = i & 8191;
        int kh = PH ? (ti/NKW)*2 : 1;
        int kw = PW ? (ti%NKW)*2 : 1;
        sW[i] = g_w1r[(kh*3+kw)*8192 + r];
    }
    __syncthreads();
    const int lane = threadIdx.x & 31;
    const int warp = threadIdx.x >> 5;
    constexpr int ROWS = PH ? H0-1 : H0;
    constexpr int COLS = PW ? W0-1 : W0;
    const int tasks = FRAMES*ROWS*COLS;
    for (int task = (blockIdx.x - firstBlk)*32 + warp; task < tasks; task += nblk*32) {
        const int ocol = task % COLS;
        const int tmp  = task / COLS;
        const int orow = tmp % ROWS;
        const int tn   = tmp / ROWS;
        const int fb   = tn*P0;
        int po[NT];
        #pragma unroll
        for (int a = 0; a < NKH; a++) {
            const int ih = PH ? (a == 0 ? orow+1 : orow) : orow;
            #pragma unroll
            for (int b = 0; b < NKW; b++) {
                const int iw = PW ? (b == 0 ? ocol+1 : ocol) : ocol;
                po[a*NKW+b] = fb + ih*W0 + iw;
            }
        }
        u64 acc = 0ull;
        #pragma unroll
        for (int ti = 0; ti < NT; ti++) {
            const int p = po[ti];
            const int c = g_cnt0[p];
            const uint8_t* lp = g_lst0 + p*128;
            const u64* wb = (const u64*)(sW + ti*8192) + lane;
            int j = 0;
            for (; j + 8 <= c; j += 8) {
                uint2 q = *(const uint2*)(lp + j);
                EV1((q.x      ) & 0xFF) EV1((q.x >>  8) & 0xFF)
                EV1((q.x >> 16) & 0xFF) EV1((q.x >> 24)       )
                EV1((q.y      ) & 0xFF) EV1((q.y >>  8) & 0xFF)
                EV1((q.y >> 16) & 0xFF) EV1((q.y >> 24)       )
            }
            if (j + 4 <= c) {
                uint32_t q = *(const uint32_t*)(lp + j);
                EV1((q      ) & 0xFF) EV1((q >>  8) & 0xFF)
                EV1((q >> 16) & 0xFF) EV1((q >> 24)       )
                j += 4;
            }
            for (; j < c; j++) EV1(lp[j]);
        }
        const int oh = PH ? 2*orow+1 : 2*orow;
        const int ow = PW ? 2*ocol+1 : 2*ocol;
        *(u64*)(g_z1 + ((size_t)tn*P1 + oh*W1 + ow)*C1 + 2*lane) = acc;
    }
}

__global__ void __launch_bounds__(1024)
k_conv1() {   // one launch, class partition proportional to event load
    extern __shared__ float sW[];
    const int blk = blockIdx.x;
    if (blk < 18)      conv1body<0,0>(sW, 0,  18);
    else if (blk < 51) conv1body<0,1>(sW, 18, 33);
    else if (blk < 84) conv1body<1,0>(sW, 51, 33);
    else               conv1body<1,1>(sW, 84, 64);
}

// ==== layer 2 conv body (merged 64-entry lists) ====
template<int PH, int PW>
__device__ __forceinline__ void conv2body(float* sW, int firstBlk, int nblk) {
    constexpr int NKH = PH ? 2 : 1;
    constexpr int NKW = PW ? 2 : 1;
    constexpr int NT = NKH*NKW;
    for (int i = threadIdx.x; i < NT*C1*C2; i += 1024) {
        int ti = i >> 11;
        int r  = i & 2047;
        int kh = PH ? (ti/NKW)*2 : 1;
        int kw = PW ? (ti%NKW)*2 : 1;
        sW[i] = g_w2r[(kh*3+kw)*2048 + r];
    }
    __syncthreads();
    const int lane = threadIdx.x & 31;
    const int warp = threadIdx.x >> 5;
    constexpr int ROWS = PH ? H1-1 : H1;
    constexpr int COLS = PW ? W1-1 : W1;
    const int tasks = FRAMES*ROWS*COLS;
    for (int task = (blockIdx.x - firstBlk)*32 + warp; task < tasks; task += nblk*32) {
        const int ocol = task % COLS;
        const int tmp  = task / COLS;
        const int orow = tmp % ROWS;
        const int tn   = tmp / ROWS;
        const int fb   = tn*P1;
        int po[NT];
        #pragma unroll
        for (int a = 0; a < NKH; a++) {
            const int ih = PH ? (a == 0 ? orow+1 : orow) : orow;
            #pragma unroll
            for (int b = 0; b < NKW; b++) {
                const int iw = PW ? (b == 0 ? ocol+1 : ocol) : ocol;
                po[a*NKW+b] = fb + ih*W1 + iw;
            }
        }
        float acc = 0.f;
        #pragma unroll
        for (int ti = 0; ti < NT; ti++) {
            const int p = po[ti];
            const int c = g_cnt1[p];
            const uint8_t* lp = g_lst1 + p*64;
            const float* wb = sW + ti*2048 + lane;
            int j = 0;
            for (; j + 8 <= c; j += 8) {
                uint2 q = *(const uint2*)(lp + j);
                EV2((q.x      ) & 0xFF) EV2((q.x >>  8) & 0xFF)
                EV2((q.x >> 16) & 0xFF) EV2((q.x >> 24)       )
                EV2((q.y      ) & 0xFF) EV2((q.y >>  8) & 0xFF)
                EV2((q.y >> 16) & 0xFF) EV2((q.y >> 24)       )
            }
            if (j + 4 <= c) {
                uint32_t q = *(const uint32_t*)(lp + j);
                EV2((q      ) & 0xFF) EV2((q >>  8) & 0xFF)
                EV2((q >> 16) & 0xFF) EV2((q >> 24)       )
                j += 4;
            }
            for (; j < c; j++) EV2(lp[j]);
        }
        const int oh = PH ? 2*orow+1 : 2*orow;
        const int ow = PW ? 2*ocol+1 : 2*ocol;
        g_z2[((size_t)tn*P2 + oh*W2 + ow)*C2 + lane] = acc;
    }
}

__global__ void __launch_bounds__(1024)
k_conv2() {
    extern __shared__ float sW[];
    const int blk = blockIdx.x;
    if (blk < 34)       conv2body<0,0>(sW, 0,   34);
    else if (blk < 101) conv2body<0,1>(sW, 34,  67);
    else if (blk < 168) conv2body<1,0>(sW, 101, 67);
    else                conv2body<1,1>(sW, 168, 128);
}

// ---- LIF layer 1: warp per (n,pix), 2 channels per lane; merged list ----
__global__ void k_lif1() {
    const int gw = blockIdx.x*4 + (threadIdx.x >> 5);   // 961 blocks x 4 warps = 3844 exact
    const int lane = threadIdx.x & 31;
    const int pix = gw % P1;
    const int n   = gw / P1;
    const uint32_t ltmask = (1u << lane) - 1u;
    float cur0=0.f, vol0=0.f, cur1=0.f, vol1=0.f;
    int cnt = 0;
    #pragma unroll 1
    for (int t = 0; t < TT; t++) {
        const int f = t*NB + n;
        const size_t zb = ((size_t)f*P1 + pix)*C1 + lane;
        float z0 = g_z1[zb];
        float z1v = g_z1[zb + 32];
        cur0 = 0.5f*cur0 + z0;  vol0 = 0.5f*vol0 + cur0;
        cur1 = 0.5f*cur1 + z1v; vol1 = 0.5f*vol1 + cur1;
        bool s0 = (vol0 >= 1.0f); vol0 = s0 ? 0.f : vol0;
        bool s1 = (vol1 >= 1.0f); vol1 = s1 ? 0.f : vol1;
        cnt += (s0 ? 1 : 0) + (s1 ? 1 : 0);
        uint32_t b0 = __ballot_sync(0xffffffffu, s0);
        uint32_t b1 = __ballot_sync(0xffffffffu, s1);
        const int p = f*P1 + pix;
        const int off = __popc(b0);
        if (s0) g_lst1[p*64 + __popc(b0 & ltmask)] = (uint8_t)lane;
        if (s1) g_lst1[p*64 + off + __popc(b1 & ltmask)] = (uint8_t)(32 + lane);
        if (lane == 0) g_cnt1[p] = (uint8_t)(off + __popc(b1));
    }
    cnt = __reduce_add_sync(0xffffffffu, cnt);
    if (lane == 0) atomicAdd(&g_cnt[0], cnt);
}

// ---- LIF layer 2 ----
__global__ void k_lif2() {
    const int idx = blockIdx.x*blockDim.x + threadIdx.x;
    const int total = NB*P2*C2;
    if (idx >= total) return;                 // total % 32 == 0
    const int c   = idx % C2;
    const int pix = (idx / C2) % P2;
    const int n   = idx / (C2*P2);
    const int lane = threadIdx.x & 31;
    const uint32_t ltmask = (1u << lane) - 1u;
    float cur = 0.f, vol = 0.f;
    int cnt = 0;
    #pragma unroll
    for (int t = 0; t < TT; t++) {
        const int f = t*NB + n;
        float zv = g_z2[((size_t)f*P2 + pix)*C2 + c];
        cur = 0.5f*cur + zv;
        vol = 0.5f*vol + cur;
        bool s = (vol >= 1.0f);
        vol = s ? 0.f : vol;
        cnt += s ? 1 : 0;
        uint32_t bal = __ballot_sync(0xffffffffu, s);
        const int p = f*P2 + pix;
        if (s) g_lst2[p*32 + __popc(bal & ltmask)] = (uint8_t)lane;
        if (lane == 0) g_cnt2[p] = (uint8_t)__popc(bal);
    }
    cnt = __reduce_add_sync(0xffffffffu, cnt);
    if (lane == 0) atomicAdd(&g_cnt[1], cnt);
}

// ---- layer 3 fused conv+LIF: thread per (n, opix), t-loop inside, writes output ----
__global__ void k_conv3lif(float* __restrict__ out) {
    __shared__ float sW[9*C2*2];
    for (int i = threadIdx.x; i < 9*C2*2; i += blockDim.x) sW[i] = g_w3r[i];
    __syncthreads();
    const int idx = blockIdx.x*blockDim.x + threadIdx.x;
    const bool valid = (idx < NB*P3);
    int cnt = 0;
    if (valid) {
        const int ow = idx % W3;
        const int oh = (idx / W3) % H3;
        const int n  = idx / P3;
        int ip[4], tb[4], ntap;
        {
            int khs[2], ihs[2], nh2; int kws[2], iws[2], nw2;
            if (oh & 1) { khs[0]=0; ihs[0]=(oh+1)>>1; khs[1]=2; ihs[1]=(oh-1)>>1; nh2=2; }
            else        { khs[0]=1; ihs[0]=oh>>1; nh2=1; }
            if (ow & 1) { kws[0]=0; iws[0]=(ow+1)>>1; kws[1]=2; iws[1]=(ow-1)>>1; nw2=2; }
            else        { kws[0]=1; iws[0]=ow>>1; nw2=1; }
            ntap = 0;
            for (int a = 0; a < nh2; a++)
                for (int b = 0; b < nw2; b++) {
                    ip[ntap] = ihs[a]*W2 + iws[b];
                    tb[ntap] = (khs[a]*3 + kws[b])*C2;
                    ntap++;
                }
        }
        float cur0=0.f, vol0=0.f, cur1=0.f, vol1=0.f;
        float res0[TT], res1[TT];
        #pragma unroll 1
        for (int t = 0; t < TT; t++) {
            const int fb = (t*NB + n)*P2;
            u64 acc = 0ull;
            #pragma unroll
            for (int k = 0; k < 4; k++) {
                if (k >= ntap) break;
                const int p = fb + ip[k];
                const int c = g_cnt2[p];
                const uint8_t* lp = g_lst2 + p*32;
                const u64* wb = (const u64*)sW + tb[k];
                for (int j = 0; j < c; j++) {
                    u64 w_ = wb[lp[j]];
                    ADD2(acc, w_);
                }
            }
            float2 zz = *(float2*)&acc;
            cur0 = 0.5f*cur0 + zz.x; vol0 = 0.5f*vol0 + cur0;
            cur1 = 0.5f*cur1 + zz.y; vol1 = 0.5f*vol1 + cur1;
            bool s0 = (vol0 >= 1.0f), s1 = (vol1 >= 1.0f);
            vol0 = s0 ? 0.f : vol0;  vol1 = s1 ? 0.f : vol1;
            res0[t] = s0 ? 1.0f : 0.0f;  res1[t] = s1 ? 1.0f : 0.0f;
            cnt += (s0 ? 1 : 0) + (s1 ? 1 : 0);
        }
        const int pix = oh*W3 + ow;
        float4* op0 = (float4*)(out + (((size_t)n*C3 + 0)*P3 + pix)*TT);
        float4* op1 = (float4*)(out + (((size_t)n*C3 + 1)*P3 + pix)*TT);
        #pragma unroll
        for (int q = 0; q < 8; q++) {
            op0[q] = make_float4(res0[4*q], res0[4*q+1], res0[4*q+2], res0[4*q+3]);
            op1[q] = make_float4(res1[4*q], res1[4*q+1], res1[4*q+2], res1[4*q+3]);
        }
    }
    cnt = __reduce_add_sync(0xffffffffu, cnt);
    if ((threadIdx.x & 31) == 0 && cnt) atomicAdd(&g_cnt[2], cnt);
}

__global__ void k_final(float* out, int off) {
    if (threadIdx.x == 0) {
        out[off+0] = (float)g_cnt[0] * (1.0f / (float)((size_t)NB*C1*P1*TT));
        out[off+1] = (float)g_cnt[1] * (1.0f / (float)((size_t)NB*C2*P2*TT));
        out[off+2] = (float)g_cnt[2] * (1.0f / (float)((size_t)NB*C3*P3*TT));
    }
}

extern "C" void kernel_launch(void* const* d_in, const int* in_sizes, int n_in,
                              void* d_out, int out_size) {
    const float* x  = (const float*)d_in[0];
    const float* w1 = (const float*)d_in[1];
    const float* w2 = (const float*)d_in[2];
    const float* w3 = (const float*)d_in[3];
    float* out = (float*)d_out;

    const int smem1 = 4*C0*C1*4;   // 131072 (oo class; lighter classes use a prefix)
    const int smem2 = 4*C1*C2*4;   // 32768
    cudaFuncSetAttribute((const void*)k_conv1,
                         cudaFuncAttributeMaxDynamicSharedMemorySize, smem1);

    const int wtot = 9*C0*C1 + 9*C1*C2 + 9*C2*C3;
    k_prep<<<128 + (wtot + 255)/256, 256>>>(x, w1, w2, w3);
    k_conv1<<<148, 1024, smem1>>>();
    k_lif1<<<961, 128>>>();
    k_conv2<<<296, 1024, smem2>>>();
    k_lif2<<<(NB*P2*C2 + 255)/256, 256>>>();
    k_conv3lif<<<(NB*P3 + 255)/256, 256>>>(out);
    k_final<<<1, 32>>>(out, out_size - 3);
}

// round 10
// speedup vs baseline: 1.3558x; 1.3558x over previous
#include <cuda_runtime.h>
#include <stdint.h>

#define TT 32
#define NB 4
#define FRAMES (TT*NB)

#define C0 128
#define H0 16
#define W0 16
#define C1 64
#define H1 31
#define W1 31
#define C2 32
#define H2 61
#define W2 61
#define C3 2
#define H3 121
#define W3 121

#define P0 (H0*W0)     // 256
#define P1 (H1*W1)     // 961
#define P2 (H2*W2)     // 3721
#define P3 (H3*W3)     // 14641

typedef unsigned long long u64;

// ---- device scratch ----
__device__ uint8_t g_cnt0[FRAMES*P0];
__device__ uint8_t g_lst0[FRAMES*P0*128];
__device__ float   g_w1r[9*C0*C1];                    // [tap][ci][co], x2 scaled
__device__ float   g_w2r[9*C1*C2];
__device__ float   g_w3r[9*C2*C3];
__device__ float   g_z1[(size_t)FRAMES*P1*C1];
__device__ uint8_t g_cnt1[FRAMES*P1];
__device__ uint8_t g_lst1[FRAMES*P1*64];
__device__ float   g_z2[(size_t)FRAMES*P2*C2];
__device__ uint8_t g_cnt2[FRAMES*P2];
__device__ uint8_t g_lst2[FRAMES*P2*32];
__device__ float   g_z3[(size_t)FRAMES*P3*C3];
__device__ int     g_cnt[3];

#define ADD2(A, W) asm("add.rn.f32x2 %0, %0, %1;" : "+l"(A) : "l"(W))

// ---- merged prep: blocks [0,128) build layer-0 lists (warp per (n,pix), no barriers);
//      blocks >= 128 rearrange weights and zero counters ----
__global__ void k_prep(const float* __restrict__ x, const float* __restrict__ w1,
                       const float* __restrict__ w2, const float* __restrict__ w3) {
    if (blockIdx.x >= 128) {
        int idx = (blockIdx.x - 128)*256 + threadIdx.x;
        if (idx < 3) g_cnt[idx] = 0;
        if (idx < 9*C0*C1) {
            int co = idx & 63;
            int ci = (idx >> 6) & 127;
            int tap = idx >> 13;
            g_w1r[idx] = 2.0f * w1[(ci*C1 + co)*9 + tap];
        } else if (idx < 9*C0*C1 + 9*C1*C2) {
            int i = idx - 9*C0*C1;
            int co = i & 31;
            int ci = (i >> 5) & 63;
            int tap = i >> 11;
            g_w2r[i] = 2.0f * w2[(ci*C2 + co)*9 + tap];
        } else if (idx < 9*C0*C1 + 9*C1*C2 + 9*C2*C3) {
            int i = idx - (9*C0*C1 + 9*C1*C2);
            int co = i & 1;
            int ci = (i >> 1) & 31;
            int tap = i >> 6;
            g_w3r[i] = 2.0f * w3[(ci*C3 + co)*9 + tap];
        }
        return;
    }
    const int lane = threadIdx.x & 31;
    const int gw = blockIdx.x*8 + (threadIdx.x >> 5);   // 1024 warps = NB*P0 exact
    const int pix = gw % P0;
    const int n   = gw / P0;
    const uint32_t ltmask = (1u << lane) - 1u;
    uint32_t tmask[4];
    #pragma unroll
    for (int w = 0; w < 4; w++) {
        const float4* xp = (const float4*)(x + (((size_t)n*C0 + w*32 + lane)*P0 + pix)*TT);
        uint32_t m = 0;
        #pragma unroll
        for (int q = 0; q < 8; q++) {
            float4 vv = xp[q];
            m |= (vv.x >= 0.5f ? 1u : 0u) << (4*q);
            m |= (vv.y >= 0.5f ? 1u : 0u) << (4*q+1);
            m |= (vv.z >= 0.5f ? 1u : 0u) << (4*q+2);
            m |= (vv.w >= 0.5f ? 1u : 0u) << (4*q+3);
        }
        tmask[w] = m;
    }
    #pragma unroll 1
    for (int t = 0; t < TT; t++) {
        const int p = (t*NB + n)*P0 + pix;
        uint8_t* lb = g_lst0 + p*128;
        int off = 0;
        #pragma unroll
        for (int w = 0; w < 4; w++) {
            bool s = (tmask[w] >> t) & 1u;
            uint32_t bal = __ballot_sync(0xffffffffu, s);
            if (s) lb[off + __popc(bal & ltmask)] = (uint8_t)(w*32 + lane);
            off += __popc(bal);
        }
        if (lane == 0) g_cnt0[p] = (uint8_t)off;
    }
}

#define EV1(I) { u64 w_ = wb[(I)*32]; ADD2(acc, w_); }

// ==== layer 1 conv body (merged list, 64 couts packed in f32x2) ====
template<int PH, int PW>
__device__ __forceinline__ void conv1body(float* sW, int firstBlk, int nblk) {
    constexpr int NKH = PH ? 2 : 1;
    constexpr int NKW = PW ? 2 : 1;
    constexpr int NT = NKH*NKW;
    for (int i = threadIdx.x; i < NT*C0*C1; i += 1024) {
        int ti = i >> 13;
        int r  = i & 8191;
        int kh = PH ? (ti/NKW)*2 : 1;
        int kw = PW ? (ti%NKW)*2 : 1;
        sW[i] = g_w1r[(kh*3+kw)*8192 + r];
    }
    __syncthreads();
    const int lane = threadIdx.x & 31;
    const int warp = threadIdx.x >> 5;
    constexpr int ROWS = PH ? H0-1 : H0;
    constexpr int COLS = PW ? W0-1 : W0;
    const int tasks = FRAMES*ROWS*COLS;
    for (int task = (blockIdx.x - firstBlk)*32 + warp; task < tasks; task += nblk*32) {
        const int ocol = task % COLS;
        const int tmp  = task / COLS;
        const int orow = tmp % ROWS;
        const int tn   = tmp / ROWS;
        const int fb   = tn*P0;
        int po[NT];
        #pragma unroll
        for (int a = 0; a < NKH; a++) {
            const int ih = PH ? (a == 0 ? orow+1 : orow) : orow;
            #pragma unroll
            for (int b = 0; b < NKW; b++) {
                const int iw = PW ? (b == 0 ? ocol+1 : ocol) : ocol;
                po[a*NKW+b] = fb + ih*W0 + iw;
            }
        }
        u64 acc = 0ull;
        #pragma unroll
        for (int ti = 0; ti < NT; ti++) {
            const int p = po[ti];
            const int c = g_cnt0[p];
            const uint8_t* lp = g_lst0 + p*128;
            const u64* wb = (const u64*)(sW + ti*8192) + lane;
            int j = 0;
            for (; j + 8 <= c; j += 8) {
                uint2 q = *(const uint2*)(lp + j);
                EV1((q.x      ) & 0xFF) EV1((q.x >>  8) & 0xFF)
                EV1((q.x >> 16) & 0xFF) EV1((q.x >> 24)       )
                EV1((q.y      ) & 0xFF) EV1((q.y >>  8) & 0xFF)
                EV1((q.y >> 16) & 0xFF) EV1((q.y >> 24)       )
            }
            if (j + 4 <= c) {
                uint32_t q = *(const uint32_t*)(lp + j);
                EV1((q      ) & 0xFF) EV1((q >>  8) & 0xFF)
                EV1((q >> 16) & 0xFF) EV1((q >> 24)       )
                j += 4;
            }
            for (; j < c; j++) EV1(lp[j]);
        }
        const int oh = PH ? 2*orow+1 : 2*orow;
        const int ow = PW ? 2*ocol+1 : 2*ocol;
        *(u64*)(g_z1 + ((size_t)tn*P1 + oh*W1 + ow)*C1 + 2*lane) = acc;
    }
}

__global__ void __launch_bounds__(1024)
k_conv1a() {   // classes ee / eo / oe  (<= 64KB smem, 2 blocks/SM)
    extern __shared__ float sW[];
    const int blk = blockIdx.x;
    if (blk < 62)       conv1body<0,0>(sW, 0,   62);
    else if (blk < 179) conv1body<0,1>(sW, 62,  117);
    else                conv1body<1,0>(sW, 179, 117);
}
__global__ void __launch_bounds__(1024)
k_conv1b() {   // class oo (128KB smem)
    extern __shared__ float sW[];
    conv1body<1,1>(sW, 0, 148);
}

// ==== layer 2 conv: 2x2 output-block gather ====
// Warp computes outputs (2i,2j),(2i,2j+1),(2i+1,2j),(2i+1,2j+1) from input
// lists (i+1,j+1),(i+1,j),(i,j+1),(i,j) processed in that order so every
// output accumulates taps in ascending (kh,kw), ci ascending within lists.
// Tap tables: sW + (kh*3+kw)*2048, compile-time LDS offsets per use.
#define UA(I) { acc11 += sWl[(I)*32]; }
#define UB(I) { const float* eb_ = sWl + (I)*32; acc10 += eb_[2048];  acc11 += eb_[4096]; }
#define UC(I) { const float* eb_ = sWl + (I)*32; acc01 += eb_[6144];  acc11 += eb_[12288]; }
#define UD(I) { const float* eb_ = sWl + (I)*32; acc00 += eb_[8192];  acc01 += eb_[10240]; \
                acc10 += eb_[14336]; acc11 += eb_[16384]; }
#define UE(I) { acc += wb[(I)*32]; }

#define ELOOP(P, U) { \
    const int c_ = g_cnt1[P]; \
    const uint8_t* lp_ = g_lst1 + (P)*64; \
    int j_ = 0; \
    for (; j_ + 4 <= c_; j_ += 4) { \
        uint32_t q_ = *(const uint32_t*)(lp_ + j_); \
        U((q_      ) & 0xFF) U((q_ >>  8) & 0xFF) \
        U((q_ >> 16) & 0xFF) U((q_ >> 24)       ) \
    } \
    for (; j_ < c_; j_++) U(lp_[j_]) \
}

__global__ void __launch_bounds__(1024)
k_conv2() {
    extern __shared__ float sW[];          // all 9 taps: [tap][ci][co] = 73728 B
    for (int i = threadIdx.x; i < 9*C1*C2; i += 1024) sW[i] = g_w2r[i];
    __syncthreads();
    const int lane = threadIdx.x & 31;
    const int warp = threadIdx.x >> 5;
    const float* sWl = sW + lane;
    const int BT  = FRAMES*30*30;          // block tasks (cover rows/cols 0..59)
    const int TOT = BT + FRAMES*121;       // + edges: row 60 (61) + col 60 (60)
    for (int task = blockIdx.x*32 + warp; task < TOT; task += gridDim.x*32) {
        if (task < BT) {
            const int j  = task % 30;
            const int i  = (task/30) % 30;
            const int tn = task / 900;
            const int fb = tn*P1;
            const int pA = fb + (i+1)*W1 + (j+1);
            const int pB = fb + (i+1)*W1 + j;
            const int pC = fb + i*W1 + (j+1);
            const int pD = fb + i*W1 + j;
            float acc00 = 0.f, acc01 = 0.f, acc10 = 0.f, acc11 = 0.f;
            ELOOP(pA, UA)
            ELOOP(pB, UB)
            ELOOP(pC, UC)
            ELOOP(pD, UD)
            const size_t zb = ((size_t)tn*P2 + (2*i)*W2 + 2*j)*C2 + lane;
            g_z2[zb]             = acc00;
            g_z2[zb + C2]        = acc01;
            g_z2[zb + W2*C2]     = acc10;
            g_z2[zb + W2*C2+C2]  = acc11;
        } else {
            const int e  = task - BT;
            const int tn = e / 121;
            const int r  = e % 121;
            int oh, ow;
            if (r < 61) { oh = 60; ow = r; } else { oh = r - 61; ow = 60; }
            int khs[2], ihs[2], nh; int kws[2], iws[2], nw;
            if (oh & 1) { khs[0]=0; ihs[0]=(oh+1)>>1; khs[1]=2; ihs[1]=(oh-1)>>1; nh=2; }
            else        { khs[0]=1; ihs[0]=oh>>1; nh=1; }
            if (ow & 1) { kws[0]=0; iws[0]=(ow+1)>>1; kws[1]=2; iws[1]=(ow-1)>>1; nw=2; }
            else        { kws[0]=1; iws[0]=ow>>1; nw=1; }
            const int fb = tn*P1;
            float acc = 0.f;
            for (int a = 0; a < nh; a++)
                for (int b = 0; b < nw; b++) {
                    const int p = fb + ihs[a]*W1 + iws[b];
                    const float* wb = sW + (khs[a]*3 + kws[b])*2048 + lane;
                    ELOOP(p, UE)
                }
            g_z2[((size_t)tn*P2 + oh*W2 + ow)*C2 + lane] = acc;
        }
    }
}

// ---- LIF layer 1: warp per (n,pix), 2 channels per lane; merged list ----
__global__ void k_lif1() {
    const int gw = blockIdx.x*4 + (threadIdx.x >> 5);   // 961 x 4 warps = 3844 exact
    const int lane = threadIdx.x & 31;
    const int pix = gw % P1;
    const int n   = gw / P1;
    const uint32_t ltmask = (1u << lane) - 1u;
    float cur0=0.f, vol0=0.f, cur1=0.f, vol1=0.f;
    int cnt = 0;
    #pragma unroll 1
    for (int t = 0; t < TT; t++) {
        const int f = t*NB + n;
        const size_t zb = ((size_t)f*P1 + pix)*C1 + lane;
        float z0 = g_z1[zb];
        float z1v = g_z1[zb + 32];
        cur0 = 0.5f*cur0 + z0;  vol0 = 0.5f*vol0 + cur0;
        cur1 = 0.5f*cur1 + z1v; vol1 = 0.5f*vol1 + cur1;
        bool s0 = (vol0 >= 1.0f); vol0 = s0 ? 0.f : vol0;
        bool s1 = (vol1 >= 1.0f); vol1 = s1 ? 0.f : vol1;
        cnt += (s0 ? 1 : 0) + (s1 ? 1 : 0);
        uint32_t b0 = __ballot_sync(0xffffffffu, s0);
        uint32_t b1 = __ballot_sync(0xffffffffu, s1);
        const int p = f*P1 + pix;
        const int off = __popc(b0);
        if (s0) g_lst1[p*64 + __popc(b0 & ltmask)] = (uint8_t)lane;
        if (s1) g_lst1[p*64 + off + __popc(b1 & ltmask)] = (uint8_t)(32 + lane);
        if (lane == 0) g_cnt1[p] = (uint8_t)(off + __popc(b1));
    }
    cnt = __reduce_add_sync(0xffffffffu, cnt);
    if (lane == 0) atomicAdd(&g_cnt[0], cnt);
}

// ---- LIF layer 2 ----
__global__ void k_lif2() {
    const int idx = blockIdx.x*blockDim.x + threadIdx.x;
    const int total = NB*P2*C2;
    if (idx >= total) return;                 // total % 32 == 0
    const int c   = idx % C2;
    const int pix = (idx / C2) % P2;
    const int n   = idx / (C2*P2);
    const int lane = threadIdx.x & 31;
    const uint32_t ltmask = (1u << lane) - 1u;
    float cur = 0.f, vol = 0.f;
    int cnt = 0;
    #pragma unroll
    for (int t = 0; t < TT; t++) {
        const int f = t*NB + n;
        float zv = g_z2[((size_t)f*P2 + pix)*C2 + c];
        cur = 0.5f*cur + zv;
        vol = 0.5f*vol + cur;
        bool s = (vol >= 1.0f);
        vol = s ? 0.f : vol;
        cnt += s ? 1 : 0;
        uint32_t bal = __ballot_sync(0xffffffffu, s);
        const int p = f*P2 + pix;
        if (s) g_lst2[p*32 + __popc(bal & ltmask)] = (uint8_t)lane;
        if (lane == 0) g_cnt2[p] = (uint8_t)__popc(bal);
    }
    cnt = __reduce_add_sync(0xffffffffu, cnt);
    if (lane == 0) atomicAdd(&g_cnt[1], cnt);
}

// ---- layer 3 conv: thread per (frame, output pixel), f32x2 accumulate ----
__global__ void k_conv3() {
    __shared__ float sW[9*C2*2];
    for (int i = threadIdx.x; i < 9*C2*2; i += blockDim.x) sW[i] = g_w3r[i];
    __syncthreads();
    int idx = blockIdx.x*blockDim.x + threadIdx.x;
    if (idx >= FRAMES*P3) return;
    int ow = idx % W3;
    int oh = (idx / W3) % H3;
    int tn = idx / P3;
    int khs[2], ihs[2], nh; int kws[2], iws[2], nw;
    if (oh & 1) { khs[0]=0; ihs[0]=(oh+1)>>1; khs[1]=2; ihs[1]=(oh-1)>>1; nh=2; }
    else        { khs[0]=1; ihs[0]=oh>>1; nh=1; }
    if (ow & 1) { kws[0]=0; iws[0]=(ow+1)>>1; kws[1]=2; iws[1]=(ow-1)>>1; nw=2; }
    else        { kws[0]=1; iws[0]=ow>>1; nw=1; }
    u64 acc = 0ull;
    for (int a = 0; a < nh; a++)
        for (int b = 0; b < nw; b++) {
            int p = tn*P2 + ihs[a]*W2 + iws[b];
            int c = g_cnt2[p];
            const uint8_t* lp = g_lst2 + p*32;
            const u64* wb = (const u64*)sW + (khs[a]*3 + kws[b])*C2;
            for (int j = 0; j < c; j++) {
                u64 w_ = wb[lp[j]];
                ADD2(acc, w_);
            }
        }
    *(u64*)(g_z3 + (size_t)idx*2) = acc;
}

// ---- final LIF: writes output [N,C,H,W,T]; warp-reduced count ----
__global__ void k_lif3out(float* __restrict__ out) {
    const int idx = blockIdx.x*blockDim.x + threadIdx.x;
    const bool valid = (idx < NB*P3);
    int cnt = 0;
    if (valid) {
        const int pix = idx % P3;
        const int n   = idx / P3;
        const size_t base    = ((size_t)n*P3 + pix)*C3;
        const size_t tstride = (size_t)NB*P3*C3;
        float cur0=0.f, vol0=0.f, cur1=0.f, vol1=0.f;
        float res0[TT], res1[TT];
        #pragma unroll
        for (int t = 0; t < TT; t++) {
            float2 zv = *(const float2*)(g_z3 + (size_t)t*tstride + base);
            cur0 = 0.5f*cur0 + zv.x; vol0 = 0.5f*vol0 + cur0;
            cur1 = 0.5f*cur1 + zv.y; vol1 = 0.5f*vol1 + cur1;
            bool s0 = (vol0 >= 1.0f), s1 = (vol1 >= 1.0f);
            vol0 = s0 ? 0.f : vol0;  vol1 = s1 ? 0.f : vol1;
            res0[t] = s0 ? 1.0f : 0.0f;  res1[t] = s1 ? 1.0f : 0.0f;
            cnt += (s0 ? 1 : 0) + (s1 ? 1 : 0);
        }
        float4* op0 = (float4*)(out + (((size_t)n*C3 + 0)*P3 + pix)*TT);
        float4* op1 = (float4*)(out + (((size_t)n*C3 + 1)*P3 + pix)*TT);
        #pragma unroll
        for (int q = 0; q < 8; q++) {
            op0[q] = make_float4(res0[4*q], res0[4*q+1], res0[4*q+2], res0[4*q+3]);
            op1[q] = make_float4(res1[4*q], res1[4*q+1], res1[4*q+2], res1[4*q+3]);
        }
    }
    cnt = __reduce_add_sync(0xffffffffu, cnt);
    if ((threadIdx.x & 31) == 0 && cnt) atomicAdd(&g_cnt[2], cnt);
}

__global__ void k_final(float* out, int off) {
    if (threadIdx.x == 0) {
        out[off+0] = (float)g_cnt[0] * (1.0f / (float)((size_t)NB*C1*P1*TT));
        out[off+1] = (float)g_cnt[1] * (1.0f / (float)((size_t)NB*C2*P2*TT));
        out[off+2] = (float)g_cnt[2] * (1.0f / (float)((size_t)NB*C3*P3*TT));
    }
}

extern "C" void kernel_launch(void* const* d_in, const int* in_sizes, int n_in,
                              void* d_out, int out_size) {
    const float* x  = (const float*)d_in[0];
    const float* w1 = (const float*)d_in[1];
    const float* w2 = (const float*)d_in[2];
    const float* w3 = (const float*)d_in[3];
    float* out = (float*)d_out;

    const int smem1a = 2*C0*C1*4;   // 65536
    const int smem1b = 4*C0*C1*4;   // 131072
    const int smem2  = 9*C1*C2*4;   // 73728
    cudaFuncSetAttribute((const void*)k_conv1a,
                         cudaFuncAttributeMaxDynamicSharedMemorySize, smem1a);
    cudaFuncSetAttribute((const void*)k_conv1b,
                         cudaFuncAttributeMaxDynamicSharedMemorySize, smem1b);
    cudaFuncSetAttribute((const void*)k_conv2,
                         cudaFuncAttributeMaxDynamicSharedMemorySize, smem2);

    const int wtot = 9*C0*C1 + 9*C1*C2 + 9*C2*C3;
    k_prep<<<128 + (wtot + 255)/256, 256>>>(x, w1, w2, w3);
    k_conv1a<<<296, 1024, smem1a>>>();
    k_conv1b<<<148, 1024, smem1b>>>();
    k_lif1<<<961, 128>>>();
    k_conv2<<<296, 1024, smem2>>>();
    k_lif2<<<(NB*P2*C2 + 255)/256, 256>>>();
    k_conv3<<<(FRAMES*P3 + 255)/256, 256>>>();
    k_lif3out<<<(NB*P3 + 255)/256, 256>>>(out);
    k_final<<<1, 32>>>(out, out_size - 3);
}

// round 11
// speedup vs baseline: 1.4264x; 1.0521x over previous
#include <cuda_runtime.h>
#include <stdint.h>

#define TT 32
#define NB 4
#define FRAMES (TT*NB)

#define C0 128
#define H0 16
#define W0 16
#define C1 64
#define H1 31
#define W1 31
#define C2 32
#define H2 61
#define W2 61
#define C3 2
#define H3 121
#define W3 121

#define P0 (H0*W0)     // 256
#define P1 (H1*W1)     // 961
#define P2 (H2*W2)     // 3721
#define P3 (H3*W3)     // 14641

typedef unsigned long long u64;

// ---- device scratch ----
__device__ uint8_t g_cnt0[FRAMES*P0];
__device__ uint8_t g_lst0[FRAMES*P0*128];
__device__ float   g_w1r[9*C0*C1];                    // [tap][ci][co], x2 scaled
__device__ float   g_w2r[9*C1*C2];
__device__ float   g_w3r[9*C2*C3];
__device__ float   g_z1[(size_t)FRAMES*P1*C1];
__device__ uint8_t g_cnt1[FRAMES*P1];
__device__ uint8_t g_lst1[FRAMES*P1*64];
__device__ float   g_z2[(size_t)FRAMES*P2*C2];
__device__ uint8_t g_cnt2[FRAMES*P2];
__device__ uint8_t g_lst2[FRAMES*P2*32];
__device__ float   g_z3[(size_t)FRAMES*P3*C3];
__device__ int     g_cnt[3];

#define ADD2(A, W) asm("add.rn.f32x2 %0, %0, %1;" : "+l"(A) : "l"(W))

// ---- merged prep: blocks [0,256) build layer-0 lists (half-warp-t per (n,pix));
//      blocks >= 256 rearrange weights and zero counters ----
__global__ void k_prep(const float* __restrict__ x, const float* __restrict__ w1,
                       const float* __restrict__ w2, const float* __restrict__ w3) {
    if (blockIdx.x >= 256) {
        int idx = (blockIdx.x - 256)*256 + threadIdx.x;
        if (idx < 3) g_cnt[idx] = 0;
        if (idx < 9*C0*C1) {
            int co = idx & 63;
            int ci = (idx >> 6) & 127;
            int tap = idx >> 13;
            g_w1r[idx] = 2.0f * w1[(ci*C1 + co)*9 + tap];
        } else if (idx < 9*C0*C1 + 9*C1*C2) {
            int i = idx - 9*C0*C1;
            int co = i & 31;
            int ci = (i >> 5) & 63;
            int tap = i >> 11;
            g_w2r[i] = 2.0f * w2[(ci*C2 + co)*9 + tap];
        } else if (idx < 9*C0*C1 + 9*C1*C2 + 9*C2*C3) {
            int i = idx - (9*C0*C1 + 9*C1*C2);
            int co = i & 1;
            int ci = (i >> 1) & 31;
            int tap = i >> 6;
            g_w3r[i] = 2.0f * w3[(ci*C3 + co)*9 + tap];
        }
        return;
    }
    const int lane = threadIdx.x & 31;
    const int gw = blockIdx.x*8 + (threadIdx.x >> 5);   // 2048 warps
    const int half = gw & 1;                             // t in [16*half, 16*half+16)
    const int pp = gw >> 1;                              // 1024 = NB*P0 exact
    const int pix = pp % P0;
    const int n   = pp / P0;
    const uint32_t ltmask = (1u << lane) - 1u;
    uint32_t tmask[4];
    #pragma unroll
    for (int w = 0; w < 4; w++) {
        const float4* xp = (const float4*)(x + (((size_t)n*C0 + w*32 + lane)*P0 + pix)*TT)
                           + half*4;
        uint32_t m = 0;
        #pragma unroll
        for (int q = 0; q < 4; q++) {
            float4 vv = xp[q];
            m |= (vv.x >= 0.5f ? 1u : 0u) << (4*q);
            m |= (vv.y >= 0.5f ? 1u : 0u) << (4*q+1);
            m |= (vv.z >= 0.5f ? 1u : 0u) << (4*q+2);
            m |= (vv.w >= 0.5f ? 1u : 0u) << (4*q+3);
        }
        tmask[w] = m;
    }
    #pragma unroll 1
    for (int tt = 0; tt < 16; tt++) {
        const int t = half*16 + tt;
        const int p = (t*NB + n)*P0 + pix;
        uint8_t* lb = g_lst0 + p*128;
        int off = 0;
        #pragma unroll
        for (int w = 0; w < 4; w++) {
            bool s = (tmask[w] >> tt) & 1u;
            uint32_t bal = __ballot_sync(0xffffffffu, s);
            if (s) lb[off + __popc(bal & ltmask)] = (uint8_t)(w*32 + lane);
            off += __popc(bal);
        }
        if (lane == 0) g_cnt0[p] = (uint8_t)off;
    }
}

#define EV1(I) { u64 w_ = wb[(I)*32]; ADD2(acc, w_); }

// ==== layer 1 conv body (merged list, 64 couts packed in f32x2) ====
template<int PH, int PW>
__device__ __forceinline__ void conv1body(float* sW, int firstBlk, int nblk) {
    constexpr int NKH = PH ? 2 : 1;
    constexpr int NKW = PW ? 2 : 1;
    constexpr int NT = NKH*NKW;
    for (int i = threadIdx.x; i < NT*C0*C1; i += 1024) {
        int ti = i >> 13;
        int r  = i & 8191;
        int kh = PH ? (ti/NKW)*2 : 1;
        int kw = PW ? (ti%NKW)*2 : 1;
        sW[i] = g_w1r[(kh*3+kw)*8192 + r];
    }
    __syncthreads();
    const int lane = threadIdx.x & 31;
    const int warp = threadIdx.x >> 5;
    constexpr int ROWS = PH ? H0-1 : H0;
    constexpr int COLS = PW ? W0-1 : W0;
    const int tasks = FRAMES*ROWS*COLS;
    for (int task = (blockIdx.x - firstBlk)*32 + warp; task < tasks; task += nblk*32) {
        const int ocol = task % COLS;
        const int tmp  = task / COLS;
        const int orow = tmp % ROWS;
        const int tn   = tmp / ROWS;
        const int fb   = tn*P0;
        int po[NT];
        #pragma unroll
        for (int a = 0; a < NKH; a++) {
            const int ih = PH ? (a == 0 ? orow+1 : orow) : orow;
            #pragma unroll
            for (int b = 0; b < NKW; b++) {
                const int iw = PW ? (b == 0 ? ocol+1 : ocol) : ocol;
                po[a*NKW+b] = fb + ih*W0 + iw;
            }
        }
        u64 acc = 0ull;
        #pragma unroll
        for (int ti = 0; ti < NT; ti++) {
            const int p = po[ti];
            const int c = g_cnt0[p];
            const uint8_t* lp = g_lst0 + p*128;
            const u64* wb = (const u64*)(sW + ti*8192) + lane;
            int j = 0;
            for (; j + 8 <= c; j += 8) {
                uint2 q = *(const uint2*)(lp + j);
                EV1((q.x      ) & 0xFF) EV1((q.x >>  8) & 0xFF)
                EV1((q.x >> 16) & 0xFF) EV1((q.x >> 24)       )
                EV1((q.y      ) & 0xFF) EV1((q.y >>  8) & 0xFF)
                EV1((q.y >> 16) & 0xFF) EV1((q.y >> 24)       )
            }
            if (j + 4 <= c) {
                uint32_t q = *(const uint32_t*)(lp + j);
                EV1((q      ) & 0xFF) EV1((q >>  8) & 0xFF)
                EV1((q >> 16) & 0xFF) EV1((q >> 24)       )
                j += 4;
            }
            for (; j < c; j++) EV1(lp[j]);
        }
        const int oh = PH ? 2*orow+1 : 2*orow;
        const int ow = PW ? 2*ocol+1 : 2*ocol;
        *(u64*)(g_z1 + ((size_t)tn*P1 + oh*W1 + ow)*C1 + 2*lane) = acc;
    }
}

__global__ void __launch_bounds__(1024)
k_conv1a() {   // classes ee / eo / oe  (<= 64KB smem, 2 blocks/SM)
    extern __shared__ float sW[];
    const int blk = blockIdx.x;
    if (blk < 62)       conv1body<0,0>(sW, 0,   62);
    else if (blk < 179) conv1body<0,1>(sW, 62,  117);
    else                conv1body<1,0>(sW, 179, 117);
}
__global__ void __launch_bounds__(1024)
k_conv1b() {   // class oo (128KB smem)
    extern __shared__ float sW[];
    conv1body<1,1>(sW, 0, 148);
}

// ==== layer 2 conv: 2x2 output-block gather (proven in R10) ====
#define UA(I) { acc11 += sWl[(I)*32]; }
#define UB(I) { const float* eb_ = sWl + (I)*32; acc10 += eb_[2048];  acc11 += eb_[4096]; }
#define UC(I) { const float* eb_ = sWl + (I)*32; acc01 += eb_[6144];  acc11 += eb_[12288]; }
#define UD(I) { const float* eb_ = sWl + (I)*32; acc00 += eb_[8192];  acc01 += eb_[10240]; \
                acc10 += eb_[14336]; acc11 += eb_[16384]; }
#define UE(I) { acc += wb[(I)*32]; }

#define ELOOP(P, U) { \
    const int c_ = g_cnt1[P]; \
    const uint8_t* lp_ = g_lst1 + (P)*64; \
    int j_ = 0; \
    for (; j_ + 4 <= c_; j_ += 4) { \
        uint32_t q_ = *(const uint32_t*)(lp_ + j_); \
        U((q_      ) & 0xFF) U((q_ >>  8) & 0xFF) \
        U((q_ >> 16) & 0xFF) U((q_ >> 24)       ) \
    } \
    for (; j_ < c_; j_++) U(lp_[j_]) \
}

__global__ void __launch_bounds__(1024)
k_conv2() {
    extern __shared__ float sW[];          // all 9 taps: [tap][ci][co] = 73728 B
    for (int i = threadIdx.x; i < 9*C1*C2; i += 1024) sW[i] = g_w2r[i];
    __syncthreads();
    const int lane = threadIdx.x & 31;
    const int warp = threadIdx.x >> 5;
    const float* sWl = sW + lane;
    const int BT  = FRAMES*30*30;
    const int TOT = BT + FRAMES*121;
    for (int task = blockIdx.x*32 + warp; task < TOT; task += gridDim.x*32) {
        if (task < BT) {
            const int j  = task % 30;
            const int i  = (task/30) % 30;
            const int tn = task / 900;
            const int fb = tn*P1;
            const int pA = fb + (i+1)*W1 + (j+1);
            const int pB = fb + (i+1)*W1 + j;
            const int pC = fb + i*W1 + (j+1);
            const int pD = fb + i*W1 + j;
            float acc00 = 0.f, acc01 = 0.f, acc10 = 0.f, acc11 = 0.f;
            ELOOP(pA, UA)
            ELOOP(pB, UB)
            ELOOP(pC, UC)
            ELOOP(pD, UD)
            const size_t zb = ((size_t)tn*P2 + (2*i)*W2 + 2*j)*C2 + lane;
            g_z2[zb]             = acc00;
            g_z2[zb + C2]        = acc01;
            g_z2[zb + W2*C2]     = acc10;
            g_z2[zb + W2*C2+C2]  = acc11;
        } else {
            const int e  = task - BT;
            const int tn = e / 121;
            const int r  = e % 121;
            int oh, ow;
            if (r < 61) { oh = 60; ow = r; } else { oh = r - 61; ow = 60; }
            int khs[2], ihs[2], nh; int kws[2], iws[2], nw;
            if (oh & 1) { khs[0]=0; ihs[0]=(oh+1)>>1; khs[1]=2; ihs[1]=(oh-1)>>1; nh=2; }
            else        { khs[0]=1; ihs[0]=oh>>1; nh=1; }
            if (ow & 1) { kws[0]=0; iws[0]=(ow+1)>>1; kws[1]=2; iws[1]=(ow-1)>>1; nw=2; }
            else        { kws[0]=1; iws[0]=ow>>1; nw=1; }
            const int fb = tn*P1;
            float acc = 0.f;
            for (int a = 0; a < nh; a++)
                for (int b = 0; b < nw; b++) {
                    const int p = fb + ihs[a]*W1 + iws[b];
                    const float* wb = sW + (khs[a]*3 + kws[b])*2048 + lane;
                    ELOOP(p, UE)
                }
            g_z2[((size_t)tn*P2 + oh*W2 + ow)*C2 + lane] = acc;
        }
    }
}

// ---- LIF layer 1: warp per (n,pix), 2 channels per lane; unroll for MLP ----
__global__ void k_lif1() {
    const int gw = blockIdx.x*4 + (threadIdx.x >> 5);   // 961 x 4 warps = 3844 exact
    const int lane = threadIdx.x & 31;
    const int pix = gw % P1;
    const int n   = gw / P1;
    const uint32_t ltmask = (1u << lane) - 1u;
    float cur0=0.f, vol0=0.f, cur1=0.f, vol1=0.f;
    int cnt = 0;
    #pragma unroll 4
    for (int t = 0; t < TT; t++) {
        const int f = t*NB + n;
        const size_t zb = ((size_t)f*P1 + pix)*C1 + lane;
        float z0 = g_z1[zb];
        float z1v = g_z1[zb + 32];
        cur0 = 0.5f*cur0 + z0;  vol0 = 0.5f*vol0 + cur0;
        cur1 = 0.5f*cur1 + z1v; vol1 = 0.5f*vol1 + cur1;
        bool s0 = (vol0 >= 1.0f); vol0 = s0 ? 0.f : vol0;
        bool s1 = (vol1 >= 1.0f); vol1 = s1 ? 0.f : vol1;
        cnt += (s0 ? 1 : 0) + (s1 ? 1 : 0);
        uint32_t b0 = __ballot_sync(0xffffffffu, s0);
        uint32_t b1 = __ballot_sync(0xffffffffu, s1);
        const int p = f*P1 + pix;
        const int off = __popc(b0);
        if (s0) g_lst1[p*64 + __popc(b0 & ltmask)] = (uint8_t)lane;
        if (s1) g_lst1[p*64 + off + __popc(b1 & ltmask)] = (uint8_t)(32 + lane);
        if (lane == 0) g_cnt1[p] = (uint8_t)(off + __popc(b1));
    }
    cnt = __reduce_add_sync(0xffffffffu, cnt);
    if (lane == 0) atomicAdd(&g_cnt[0], cnt);
}

// ---- LIF layer 2 ----
__global__ void k_lif2() {
    const int idx = blockIdx.x*blockDim.x + threadIdx.x;
    const int total = NB*P2*C2;
    if (idx >= total) return;                 // total % 32 == 0
    const int c   = idx % C2;
    const int pix = (idx / C2) % P2;
    const int n   = idx / (C2*P2);
    const int lane = threadIdx.x & 31;
    const uint32_t ltmask = (1u << lane) - 1u;
    float cur = 0.f, vol = 0.f;
    int cnt = 0;
    #pragma unroll
    for (int t = 0; t < TT; t++) {
        const int f = t*NB + n;
        float zv = g_z2[((size_t)f*P2 + pix)*C2 + c];
        cur = 0.5f*cur + zv;
        vol = 0.5f*vol + cur;
        bool s = (vol >= 1.0f);
        vol = s ? 0.f : vol;
        cnt += s ? 1 : 0;
        uint32_t bal = __ballot_sync(0xffffffffu, s);
        const int p = f*P2 + pix;
        if (s) g_lst2[p*32 + __popc(bal & ltmask)] = (uint8_t)lane;
        if (lane == 0) g_cnt2[p] = (uint8_t)__popc(bal);
    }
    cnt = __reduce_add_sync(0xffffffffu, cnt);
    if (lane == 0) atomicAdd(&g_cnt[1], cnt);
}

// ==== layer 3 conv: 2x2 output-block gather, thread per block ====
// Same list order (A,B,C,D) and tap->acc mapping as conv2:
// a11<-taps 0,2,6,8; a01<-3,5; a10<-1,7; a00<-4. Weights u64 per (tap,ci).
__device__ u64 __forceinline__ ld_sw64(const u64* p) { return *p; }
#define VA(I) { ADD2(a11, sW64[      (I)]); }
#define VB(I) { ADD2(a10, sW64[ 32 + (I)]); ADD2(a11, sW64[ 64 + (I)]); }
#define VC(I) { ADD2(a01, sW64[ 96 + (I)]); ADD2(a11, sW64[192 + (I)]); }
#define VD(I) { ADD2(a00, sW64[128 + (I)]); ADD2(a01, sW64[160 + (I)]); \
                ADD2(a10, sW64[224 + (I)]); ADD2(a11, sW64[256 + (I)]); }
#define VE(I) { u64 w_ = wb[(I)]; ADD2(acc, w_); }

#define ELOOP3(P, U) { \
    const int c_ = g_cnt2[P]; \
    const uint8_t* lp_ = g_lst2 + (P)*32; \
    int j_ = 0; \
    for (; j_ + 4 <= c_; j_ += 4) { \
        uint32_t q_ = *(const uint32_t*)(lp_ + j_); \
        U((q_      ) & 0xFF) U((q_ >>  8) & 0xFF) \
        U((q_ >> 16) & 0xFF) U((q_ >> 24)       ) \
    } \
    for (; j_ < c_; j_++) U(lp_[j_]) \
}

__global__ void k_conv3() {
    __shared__ u64 sW64[9*C2];
    for (int i = threadIdx.x; i < 9*C2*2; i += blockDim.x)
        ((float*)sW64)[i] = g_w3r[i];
    __syncthreads();
    const int task = blockIdx.x*blockDim.x + threadIdx.x;
    const int BT  = FRAMES*60*60;
    const int TOT = BT + FRAMES*241;
    if (task >= TOT) return;
    if (task < BT) {
        const int j  = task % 60;
        const int i  = (task/60) % 60;
        const int tn = task / 3600;
        const int fb = tn*P2;
        const int pA = fb + (i+1)*W2 + (j+1);
        const int pB = fb + (i+1)*W2 + j;
        const int pC = fb + i*W2 + (j+1);
        const int pD = fb + i*W2 + j;
        u64 a00=0ull, a01=0ull, a10=0ull, a11=0ull;
        ELOOP3(pA, VA)
        ELOOP3(pB, VB)
        ELOOP3(pC, VC)
        ELOOP3(pD, VD)
        const size_t zb = ((size_t)tn*P3 + (2*i)*W3 + 2*j)*2;
        *(u64*)(g_z3 + zb)          = a00;
        *(u64*)(g_z3 + zb + 2)      = a01;
        *(u64*)(g_z3 + zb + W3*2)   = a10;
        *(u64*)(g_z3 + zb + W3*2+2) = a11;
    } else {
        const int e  = task - BT;
        const int tn = e / 241;
        const int r  = e % 241;
        int oh, ow;
        if (r < 121) { oh = 120; ow = r; } else { oh = r - 121; ow = 120; }
        int khs[2], ihs[2], nh; int kws[2], iws[2], nw;
        if (oh & 1) { khs[0]=0; ihs[0]=(oh+1)>>1; khs[1]=2; ihs[1]=(oh-1)>>1; nh=2; }
        else        { khs[0]=1; ihs[0]=oh>>1; nh=1; }
        if (ow & 1) { kws[0]=0; iws[0]=(ow+1)>>1; kws[1]=2; iws[1]=(ow-1)>>1; nw=2; }
        else        { kws[0]=1; iws[0]=ow>>1; nw=1; }
        u64 acc = 0ull;
        for (int a = 0; a < nh; a++)
            for (int b = 0; b < nw; b++) {
                const int p = tn*P2 + ihs[a]*W2 + iws[b];
                const u64* wb = sW64 + (khs[a]*3 + kws[b])*C2;
                ELOOP3(p, VE)
            }
        *(u64*)(g_z3 + ((size_t)tn*P3 + oh*W3 + ow)*2) = acc;
    }
}

// ---- final LIF: bitpacked spikes, writes output [N,C,H,W,T] ----
__global__ void k_lif3out(float* __restrict__ out) {
    const int idx = blockIdx.x*blockDim.x + threadIdx.x;
    const bool valid = (idx < NB*P3);
    int cnt = 0;
    if (valid) {
        const int pix = idx % P3;
        const int n   = idx / P3;
        const size_t base    = ((size_t)n*P3 + pix)*C3;
        const size_t tstride = (size_t)NB*P3*C3;
        float cur0=0.f, vol0=0.f, cur1=0.f, vol1=0.f;
        uint32_t bits0 = 0, bits1 = 0;
        #pragma unroll
        for (int t = 0; t < TT; t++) {
            float2 zv = *(const float2*)(g_z3 + (size_t)t*tstride + base);
            cur0 = 0.5f*cur0 + zv.x; vol0 = 0.5f*vol0 + cur0;
            cur1 = 0.5f*cur1 + zv.y; vol1 = 0.5f*vol1 + cur1;
            bool s0 = (vol0 >= 1.0f), s1 = (vol1 >= 1.0f);
            vol0 = s0 ? 0.f : vol0;  vol1 = s1 ? 0.f : vol1;
            bits0 |= (s0 ? 1u : 0u) << t;
            bits1 |= (s1 ? 1u : 0u) << t;
        }
        cnt = __popc(bits0) + __popc(bits1);
        float4* op0 = (float4*)(out + (((size_t)n*C3 + 0)*P3 + pix)*TT);
        float4* op1 = (float4*)(out + (((size_t)n*C3 + 1)*P3 + pix)*TT);
        #pragma unroll
        for (int q = 0; q < 8; q++) {
            op0[q] = make_float4((float)((bits0 >> (4*q  )) & 1u),
                                 (float)((bits0 >> (4*q+1)) & 1u),
                                 (float)((bits0 >> (4*q+2)) & 1u),
                                 (float)((bits0 >> (4*q+3)) & 1u));
            op1[q] = make_float4((float)((bits1 >> (4*q  )) & 1u),
                                 (float)((bits1 >> (4*q+1)) & 1u),
                                 (float)((bits1 >> (4*q+2)) & 1u),
                                 (float)((bits1 >> (4*q+3)) & 1u));
        }
    }
    cnt = __reduce_add_sync(0xffffffffu, cnt);
    if ((threadIdx.x & 31) == 0 && cnt) atomicAdd(&g_cnt[2], cnt);
}

__global__ void k_final(float* out, int off) {
    if (threadIdx.x == 0) {
        out[off+0] = (float)g_cnt[0] * (1.0f / (float)((size_t)NB*C1*P1*TT));
        out[off+1] = (float)g_cnt[1] * (1.0f / (float)((size_t)NB*C2*P2*TT));
        out[off+2] = (float)g_cnt[2] * (1.0f / (float)((size_t)NB*C3*P3*TT));
    }
}

extern "C" void kernel_launch(void* const* d_in, const int* in_sizes, int n_in,
                              void* d_out, int out_size) {
    const float* x  = (const float*)d_in[0];
    const float* w1 = (const float*)d_in[1];
    const float* w2 = (const float*)d_in[2];
    const float* w3 = (const float*)d_in[3];
    float* out = (float*)d_out;

    const int smem1a = 2*C0*C1*4;   // 65536
    const int smem1b = 4*C0*C1*4;   // 131072
    const int smem2  = 9*C1*C2*4;   // 73728
    cudaFuncSetAttribute((const void*)k_conv1a,
                         cudaFuncAttributeMaxDynamicSharedMemorySize, smem1a);
    cudaFuncSetAttribute((const void*)k_conv1b,
                         cudaFuncAttributeMaxDynamicSharedMemorySize, smem1b);
    cudaFuncSetAttribute((const void*)k_conv2,
                         cudaFuncAttributeMaxDynamicSharedMemorySize, smem2);

    const int wtot = 9*C0*C1 + 9*C1*C2 + 9*C2*C3;
    k_prep<<<256 + (wtot + 255)/256, 256>>>(x, w1, w2, w3);
    k_conv1a<<<296, 1024, smem1a>>>();
    k_conv1b<<<148, 1024, smem1b>>>();
    k_lif1<<<961, 128>>>();
    k_conv2<<<296, 1024, smem2>>>();
    k_lif2<<<(NB*P2*C2 + 255)/256, 256>>>();
    k_conv3<<<(FRAMES*(60*60 + 241) + 255)/256, 256>>>();
    k_lif3out<<<(NB*P3 + 255)/256, 256>>>(out);
    k_final<<<1, 32>>>(out, out_size - 3);
}

// round 12
// speedup vs baseline: 1.4617x; 1.0247x over previous
#include <cuda_runtime.h>
#include <stdint.h>

#define TT 32
#define NB 4
#define FRAMES (TT*NB)

#define C0 128
#define H0 16
#define W0 16
#define C1 64
#define H1 31
#define W1 31
#define C2 32
#define H2 61
#define W2 61
#define C3 2
#define H3 121
#define W3 121

#define P0 (H0*W0)     // 256
#define P1 (H1*W1)     // 961
#define P2 (H2*W2)     // 3721
#define P3 (H3*W3)     // 14641

typedef unsigned long long u64;

// ---- device scratch ----
__device__ uint8_t g_cnt0[FRAMES*P0];
__device__ uint8_t g_lst0[FRAMES*P0*128];
__device__ float   g_w1r[9*C0*C1];                    // [tap][ci][co], x2 scaled
__device__ float   g_w2r[9*C1*C2];
__device__ float   g_w3r[9*C2*C3];
__device__ float   g_z1[(size_t)FRAMES*P1*C1];
__device__ uint8_t g_cnt1[FRAMES*P1];
__device__ uint8_t g_lst1[FRAMES*P1*64];
__device__ float   g_z2[(size_t)FRAMES*P2*C2];
__device__ uint8_t g_cnt2[FRAMES*P2];
__device__ uint8_t g_lst2[FRAMES*P2*32];
__device__ float   g_z3[(size_t)FRAMES*P3*C3];
__device__ int     g_cnt[3];

#define ADD2(A, W) asm("add.rn.f32x2 %0, %0, %1;" : "+l"(A) : "l"(W))

// ---- merged prep: blocks [0,256) build layer-0 lists (half-warp-t per (n,pix));
//      blocks >= 256 rearrange weights and zero counters ----
__global__ void k_prep(const float* __restrict__ x, const float* __restrict__ w1,
                       const float* __restrict__ w2, const float* __restrict__ w3) {
    if (blockIdx.x >= 256) {
        int idx = (blockIdx.x - 256)*256 + threadIdx.x;
        if (idx < 3) g_cnt[idx] = 0;
        if (idx < 9*C0*C1) {
            int co = idx & 63;
            int ci = (idx >> 6) & 127;
            int tap = idx >> 13;
            g_w1r[idx] = 2.0f * w1[(ci*C1 + co)*9 + tap];
        } else if (idx < 9*C0*C1 + 9*C1*C2) {
            int i = idx - 9*C0*C1;
            int co = i & 31;
            int ci = (i >> 5) & 63;
            int tap = i >> 11;
            g_w2r[i] = 2.0f * w2[(ci*C2 + co)*9 + tap];
        } else if (idx < 9*C0*C1 + 9*C1*C2 + 9*C2*C3) {
            int i = idx - (9*C0*C1 + 9*C1*C2);
            int co = i & 1;
            int ci = (i >> 1) & 31;
            int tap = i >> 6;
            g_w3r[i] = 2.0f * w3[(ci*C3 + co)*9 + tap];
        }
        return;
    }
    const int lane = threadIdx.x & 31;
    const int gw = blockIdx.x*8 + (threadIdx.x >> 5);   // 2048 warps
    const int half = gw & 1;                             // t in [16*half, 16*half+16)
    const int pp = gw >> 1;                              // 1024 = NB*P0 exact
    const int pix = pp % P0;
    const int n   = pp / P0;
    const uint32_t ltmask = (1u << lane) - 1u;
    uint32_t tmask[4];
    #pragma unroll
    for (int w = 0; w < 4; w++) {
        const float4* xp = (const float4*)(x + (((size_t)n*C0 + w*32 + lane)*P0 + pix)*TT)
                           + half*4;
        uint32_t m = 0;
        #pragma unroll
        for (int q = 0; q < 4; q++) {
            float4 vv = xp[q];
            m |= (vv.x >= 0.5f ? 1u : 0u) << (4*q);
            m |= (vv.y >= 0.5f ? 1u : 0u) << (4*q+1);
            m |= (vv.z >= 0.5f ? 1u : 0u) << (4*q+2);
            m |= (vv.w >= 0.5f ? 1u : 0u) << (4*q+3);
        }
        tmask[w] = m;
    }
    #pragma unroll 1
    for (int tt = 0; tt < 16; tt++) {
        const int t = half*16 + tt;
        const int p = (t*NB + n)*P0 + pix;
        uint8_t* lb = g_lst0 + p*128;
        int off = 0;
        #pragma unroll
        for (int w = 0; w < 4; w++) {
            bool s = (tmask[w] >> tt) & 1u;
            uint32_t bal = __ballot_sync(0xffffffffu, s);
            if (s) lb[off + __popc(bal & ltmask)] = (uint8_t)(w*32 + lane);
            off += __popc(bal);
        }
        if (lane == 0) g_cnt0[p] = (uint8_t)off;
    }
}

#define EV1(I) { u64 w_ = wb[(I)*32]; ADD2(acc, w_); }

// ==== layer 1 conv body (merged list, 64 couts packed in f32x2) ====
template<int PH, int PW>
__device__ __forceinline__ void conv1body(float* sW, int firstBlk, int nblk) {
    constexpr int NKH = PH ? 2 : 1;
    constexpr int NKW = PW ? 2 : 1;
    constexpr int NT = NKH*NKW;
    for (int i = threadIdx.x; i < NT*C0*C1; i += 1024) {
        int ti = i >> 13;
        int r  = i & 8191;
        int kh = PH ? (ti/NKW)*2 : 1;
        int kw = PW ? (ti%NKW)*2 : 1;
        sW[i] = g_w1r[(kh*3+kw)*8192 + r];
    }
    __syncthreads();
    const int lane = threadIdx.x & 31;
    const int warp = threadIdx.x >> 5;
    constexpr int ROWS = PH ? H0-1 : H0;
    constexpr int COLS = PW ? W0-1 : W0;
    const int tasks = FRAMES*ROWS*COLS;
    for (int task = (blockIdx.x - firstBlk)*32 + warp; task < tasks; task += nblk*32) {
        const int ocol = task % COLS;
        const int tmp  = task / COLS;
        const int orow = tmp % ROWS;
        const int tn   = tmp / ROWS;
        const int fb   = tn*P0;
        int po[NT];
        #pragma unroll
        for (int a = 0; a < NKH; a++) {
            const int ih = PH ? (a == 0 ? orow+1 : orow) : orow;
            #pragma unroll
            for (int b = 0; b < NKW; b++) {
                const int iw = PW ? (b == 0 ? ocol+1 : ocol) : ocol;
                po[a*NKW+b] = fb + ih*W0 + iw;
            }
        }
        u64 acc = 0ull;
        #pragma unroll
        for (int ti = 0; ti < NT; ti++) {
            const int p = po[ti];
            const int c = g_cnt0[p];
            const uint8_t* lp = g_lst0 + p*128;
            const u64* wb = (const u64*)(sW + ti*8192) + lane;
            int j = 0;
            for (; j + 8 <= c; j += 8) {
                uint2 q = *(const uint2*)(lp + j);
                EV1((q.x      ) & 0xFF) EV1((q.x >>  8) & 0xFF)
                EV1((q.x >> 16) & 0xFF) EV1((q.x >> 24)       )
                EV1((q.y      ) & 0xFF) EV1((q.y >>  8) & 0xFF)
                EV1((q.y >> 16) & 0xFF) EV1((q.y >> 24)       )
            }
            if (j + 4 <= c) {
                uint32_t q = *(const uint32_t*)(lp + j);
                EV1((q      ) & 0xFF) EV1((q >>  8) & 0xFF)
                EV1((q >> 16) & 0xFF) EV1((q >> 24)       )
                j += 4;
            }
            for (; j < c; j++) EV1(lp[j]);
        }
        const int oh = PH ? 2*orow+1 : 2*orow;
        const int ow = PW ? 2*ocol+1 : 2*ocol;
        *(u64*)(g_z1 + ((size_t)tn*P1 + oh*W1 + ow)*C1 + 2*lane) = acc;
    }
}

__global__ void __launch_bounds__(1024)
k_conv1a() {   // classes ee / eo / oe  (<= 64KB smem, 2 blocks/SM)
    extern __shared__ float sW[];
    const int blk = blockIdx.x;
    if (blk < 62)       conv1body<0,0>(sW, 0,   62);
    else if (blk < 179) conv1body<0,1>(sW, 62,  117);
    else                conv1body<1,0>(sW, 179, 117);
}
__global__ void __launch_bounds__(1024)
k_conv1b() {   // class oo (128KB smem)
    extern __shared__ float sW[];
    conv1body<1,1>(sW, 0, 148);
}

// ==== layer 2 conv: 2x2 output-block gather (proven) ====
#define UA(I) { acc11 += sWl[(I)*32]; }
#define UB(I) { const float* eb_ = sWl + (I)*32; acc10 += eb_[2048];  acc11 += eb_[4096]; }
#define UC(I) { const float* eb_ = sWl + (I)*32; acc01 += eb_[6144];  acc11 += eb_[12288]; }
#define UD(I) { const float* eb_ = sWl + (I)*32; acc00 += eb_[8192];  acc01 += eb_[10240]; \
                acc10 += eb_[14336]; acc11 += eb_[16384]; }
#define UE(I) { acc += wb[(I)*32]; }

#define ELOOP(P, U) { \
    const int c_ = g_cnt1[P]; \
    const uint8_t* lp_ = g_lst1 + (P)*64; \
    int j_ = 0; \
    for (; j_ + 4 <= c_; j_ += 4) { \
        uint32_t q_ = *(const uint32_t*)(lp_ + j_); \
        U((q_      ) & 0xFF) U((q_ >>  8) & 0xFF) \
        U((q_ >> 16) & 0xFF) U((q_ >> 24)       ) \
    } \
    for (; j_ < c_; j_++) U(lp_[j_]) \
}

__global__ void __launch_bounds__(1024)
k_conv2() {
    extern __shared__ float sW[];          // all 9 taps: 73728 B
    for (int i = threadIdx.x; i < 9*C1*C2; i += 1024) sW[i] = g_w2r[i];
    __syncthreads();
    const int lane = threadIdx.x & 31;
    const int warp = threadIdx.x >> 5;
    const float* sWl = sW + lane;
    const int BT  = FRAMES*30*30;
    const int TOT = BT + FRAMES*121;
    for (int task = blockIdx.x*32 + warp; task < TOT; task += gridDim.x*32) {
        if (task < BT) {
            const int j  = task % 30;
            const int i  = (task/30) % 30;
            const int tn = task / 900;
            const int fb = tn*P1;
            const int pA = fb + (i+1)*W1 + (j+1);
            const int pB = fb + (i+1)*W1 + j;
            const int pC = fb + i*W1 + (j+1);
            const int pD = fb + i*W1 + j;
            float acc00 = 0.f, acc01 = 0.f, acc10 = 0.f, acc11 = 0.f;
            ELOOP(pA, UA)
            ELOOP(pB, UB)
            ELOOP(pC, UC)
            ELOOP(pD, UD)
            const size_t zb = ((size_t)tn*P2 + (2*i)*W2 + 2*j)*C2 + lane;
            g_z2[zb]             = acc00;
            g_z2[zb + C2]        = acc01;
            g_z2[zb + W2*C2]     = acc10;
            g_z2[zb + W2*C2+C2]  = acc11;
        } else {
            const int e  = task - BT;
            const int tn = e / 121;
            const int r  = e % 121;
            int oh, ow;
            if (r < 61) { oh = 60; ow = r; } else { oh = r - 61; ow = 60; }
            int khs[2], ihs[2], nh; int kws[2], iws[2], nw;
            if (oh & 1) { khs[0]=0; ihs[0]=(oh+1)>>1; khs[1]=2; ihs[1]=(oh-1)>>1; nh=2; }
            else        { khs[0]=1; ihs[0]=oh>>1; nh=1; }
            if (ow & 1) { kws[0]=0; iws[0]=(ow+1)>>1; kws[1]=2; iws[1]=(ow-1)>>1; nw=2; }
            else        { kws[0]=1; iws[0]=ow>>1; nw=1; }
            const int fb = tn*P1;
            float acc = 0.f;
            for (int a = 0; a < nh; a++)
                for (int b = 0; b < nw; b++) {
                    const int p = fb + ihs[a]*W1 + iws[b];
                    const float* wb = sW + (khs[a]*3 + kws[b])*2048 + lane;
                    ELOOP(p, UE)
                }
            g_z2[((size_t)tn*P2 + oh*W2 + ow)*C2 + lane] = acc;
        }
    }
}

// ---- LIF layer 1: warp per (n,pix); lane = channel pair (2l, 2l+1), u64 loads ----
__global__ void k_lif1() {
    const int gw = blockIdx.x*4 + (threadIdx.x >> 5);   // 961 x 4 warps = 3844 exact
    const int lane = threadIdx.x & 31;
    const int pix = gw % P1;
    const int n   = gw / P1;
    const uint32_t ltmask = (1u << lane) - 1u;
    float cur0=0.f, vol0=0.f, cur1=0.f, vol1=0.f;
    int cnt = 0;
    #pragma unroll 4
    for (int t = 0; t < TT; t++) {
        const int f = t*NB + n;
        u64 zp = *(const u64*)(g_z1 + ((size_t)f*P1 + pix)*C1 + 2*lane);
        float2 zz = *(float2*)&zp;
        cur0 = 0.5f*cur0 + zz.x; vol0 = 0.5f*vol0 + cur0;   // channel 2*lane
        cur1 = 0.5f*cur1 + zz.y; vol1 = 0.5f*vol1 + cur1;   // channel 2*lane+1
        bool s0 = (vol0 >= 1.0f); vol0 = s0 ? 0.f : vol0;
        bool s1 = (vol1 >= 1.0f); vol1 = s1 ? 0.f : vol1;
        cnt += (s0 ? 1 : 0) + (s1 ? 1 : 0);
        uint32_t b0 = __ballot_sync(0xffffffffu, s0);
        uint32_t b1 = __ballot_sync(0xffffffffu, s1);
        const int p = f*P1 + pix;
        // ascending channel order: ch 2l position = spikes among channels < 2l
        const int off0 = __popc(b0 & ltmask) + __popc(b1 & ltmask);
        if (s0) g_lst1[p*64 + off0] = (uint8_t)(2*lane);
        if (s1) g_lst1[p*64 + off0 + (s0 ? 1 : 0)] = (uint8_t)(2*lane + 1);
        if (lane == 0) g_cnt1[p] = (uint8_t)(__popc(b0) + __popc(b1));
    }
    cnt = __reduce_add_sync(0xffffffffu, cnt);
    if (lane == 0) atomicAdd(&g_cnt[0], cnt);
}

// ---- LIF layer 2: warp covers TWO pixels (half-warp each), u64 loads ----
__global__ void k_lif2() {
    const int gw = blockIdx.x*(blockDim.x >> 5) + (threadIdx.x >> 5);
    const int lane = threadIdx.x & 31;
    const int half = lane >> 4;              // 0: lanes 0-15, 1: lanes 16-31
    const int j    = lane & 15;              // channel pair (2j, 2j+1)
    const int pix2 = gw*2 + half;            // pixel index in [0, NB*P2)
    if (pix2 >= NB*P2) return;               // NB*P2 even -> warps fully in/out
    const int pix = pix2 % P2;
    const int n   = pix2 / P2;
    const uint32_t hmask  = half ? 0xFFFF0000u : 0x0000FFFFu;
    const uint32_t ltmask = ((1u << lane) - 1u) & hmask;
    float cur0=0.f, vol0=0.f, cur1=0.f, vol1=0.f;
    int cnt = 0;
    #pragma unroll 4
    for (int t = 0; t < TT; t++) {
        const int f = t*NB + n;
        u64 zp = *(const u64*)(g_z2 + ((size_t)f*P2 + pix)*C2 + 2*j);
        float2 zz = *(float2*)&zp;
        cur0 = 0.5f*cur0 + zz.x; vol0 = 0.5f*vol0 + cur0;   // channel 2j
        cur1 = 0.5f*cur1 + zz.y; vol1 = 0.5f*vol1 + cur1;   // channel 2j+1
        bool s0 = (vol0 >= 1.0f); vol0 = s0 ? 0.f : vol0;
        bool s1 = (vol1 >= 1.0f); vol1 = s1 ? 0.f : vol1;
        cnt += (s0 ? 1 : 0) + (s1 ? 1 : 0);
        uint32_t b0 = __ballot_sync(0xffffffffu, s0) & hmask;
        uint32_t b1 = __ballot_sync(0xffffffffu, s1) & hmask;
        const int p = f*P2 + pix;
        const int off0 = __popc(b0 & ltmask) + __popc(b1 & ltmask);
        if (s0) g_lst2[p*32 + off0] = (uint8_t)(2*j);
        if (s1) g_lst2[p*32 + off0 + (s0 ? 1 : 0)] = (uint8_t)(2*j + 1);
        if (j == 0) g_cnt2[p] = (uint8_t)(__popc(b0) + __popc(b1));
    }
    cnt = __reduce_add_sync(0xffffffffu, cnt);
    if (lane == 0) atomicAdd(&g_cnt[1], cnt);
}

// ==== layer 3 conv: 2x2 output-block gather (proven) ====
#define VA(I) { ADD2(a11, sW64[      (I)]); }
#define VB(I) { ADD2(a10, sW64[ 32 + (I)]); ADD2(a11, sW64[ 64 + (I)]); }
#define VC(I) { ADD2(a01, sW64[ 96 + (I)]); ADD2(a11, sW64[192 + (I)]); }
#define VD(I) { ADD2(a00, sW64[128 + (I)]); ADD2(a01, sW64[160 + (I)]); \
                ADD2(a10, sW64[224 + (I)]); ADD2(a11, sW64[256 + (I)]); }
#define VE(I) { u64 w_ = wb[(I)]; ADD2(acc, w_); }

#define ELOOP3(P, U) { \
    const int c_ = g_cnt2[P]; \
    const uint8_t* lp_ = g_lst2 + (P)*32; \
    int j_ = 0; \
    for (; j_ + 4 <= c_; j_ += 4) { \
        uint32_t q_ = *(const uint32_t*)(lp_ + j_); \
        U((q_      ) & 0xFF) U((q_ >>  8) & 0xFF) \
        U((q_ >> 16) & 0xFF) U((q_ >> 24)       ) \
    } \
    for (; j_ < c_; j_++) U(lp_[j_]) \
}

__global__ void k_conv3() {
    __shared__ u64 sW64[9*C2];
    for (int i = threadIdx.x; i < 9*C2*2; i += blockDim.x)
        ((float*)sW64)[i] = g_w3r[i];
    __syncthreads();
    const int task = blockIdx.x*blockDim.x + threadIdx.x;
    const int BT  = FRAMES*60*60;
    const int TOT = BT + FRAMES*241;
    if (task >= TOT) return;
    if (task < BT) {
        const int j  = task % 60;
        const int i  = (task/60) % 60;
        const int tn = task / 3600;
        const int fb = tn*P2;
        const int pA = fb + (i+1)*W2 + (j+1);
        const int pB = fb + (i+1)*W2 + j;
        const int pC = fb + i*W2 + (j+1);
        const int pD = fb + i*W2 + j;
        u64 a00=0ull, a01=0ull, a10=0ull, a11=0ull;
        ELOOP3(pA, VA)
        ELOOP3(pB, VB)
        ELOOP3(pC, VC)
        ELOOP3(pD, VD)
        const size_t zb = ((size_t)tn*P3 + (2*i)*W3 + 2*j)*2;
        *(u64*)(g_z3 + zb)          = a00;
        *(u64*)(g_z3 + zb + 2)      = a01;
        *(u64*)(g_z3 + zb + W3*2)   = a10;
        *(u64*)(g_z3 + zb + W3*2+2) = a11;
    } else {
        const int e  = task - BT;
        const int tn = e / 241;
        const int r  = e % 241;
        int oh, ow;
        if (r < 121) { oh = 120; ow = r; } else { oh = r - 121; ow = 120; }
        int khs[2], ihs[2], nh; int kws[2], iws[2], nw;
        if (oh & 1) { khs[0]=0; ihs[0]=(oh+1)>>1; khs[1]=2; ihs[1]=(oh-1)>>1; nh=2; }
        else        { khs[0]=1; ihs[0]=oh>>1; nh=1; }
        if (ow & 1) { kws[0]=0; iws[0]=(ow+1)>>1; kws[1]=2; iws[1]=(ow-1)>>1; nw=2; }
        else        { kws[0]=1; iws[0]=ow>>1; nw=1; }
        u64 acc = 0ull;
        for (int a = 0; a < nh; a++)
            for (int b = 0; b < nw; b++) {
                const int p = tn*P2 + ihs[a]*W2 + iws[b];
                const u64* wb = sW64 + (khs[a]*3 + kws[b])*C2;
                ELOOP3(p, VE)
            }
        *(u64*)(g_z3 + ((size_t)tn*P3 + oh*W3 + ow)*2) = acc;
    }
}

// ---- final LIF: bitpacked spikes, writes output [N,C,H,W,T] ----
__global__ void k_lif3out(float* __restrict__ out) {
    const int idx = blockIdx.x*blockDim.x + threadIdx.x;
    const bool valid = (idx < NB*P3);
    int cnt = 0;
    if (valid) {
        const int pix = idx % P3;
        const int n   = idx / P3;
        const size_t base    = ((size_t)n*P3 + pix)*C3;
        const size_t tstride = (size_t)NB*P3*C3;
        float cur0=0.f, vol0=0.f, cur1=0.f, vol1=0.f;
        uint32_t bits0 = 0, bits1 = 0;
        #pragma unroll
        for (int t = 0; t < TT; t++) {
            float2 zv = *(const float2*)(g_z3 + (size_t)t*tstride + base);
            cur0 = 0.5f*cur0 + zv.x; vol0 = 0.5f*vol0 + cur0;
            cur1 = 0.5f*cur1 + zv.y; vol1 = 0.5f*vol1 + cur1;
            bool s0 = (vol0 >= 1.0f), s1 = (vol1 >= 1.0f);
            vol0 = s0 ? 0.f : vol0;  vol1 = s1 ? 0.f : vol1;
            bits0 |= (s0 ? 1u : 0u) << t;
            bits1 |= (s1 ? 1u : 0u) << t;
        }
        cnt = __popc(bits0) + __popc(bits1);
        float4* op0 = (float4*)(out + (((size_t)n*C3 + 0)*P3 + pix)*TT);
        float4* op1 = (float4*)(out + (((size_t)n*C3 + 1)*P3 + pix)*TT);
        #pragma unroll
        for (int q = 0; q < 8; q++) {
            op0[q] = make_float4((float)((bits0 >> (4*q  )) & 1u),
                                 (float)((bits0 >> (4*q+1)) & 1u),
                                 (float)((bits0 >> (4*q+2)) & 1u),
                                 (float)((bits0 >> (4*q+3)) & 1u));
            op1[q] = make_float4((float)((bits1 >> (4*q  )) & 1u),
                                 (float)((bits1 >> (4*q+1)) & 1u),
                                 (float)((bits1 >> (4*q+2)) & 1u),
                                 (float)((bits1 >> (4*q+3)) & 1u));
        }
    }
    cnt = __reduce_add_sync(0xffffffffu, cnt);
    if ((threadIdx.x & 31) == 0 && cnt) atomicAdd(&g_cnt[2], cnt);
}

__global__ void k_final(float* out, int off) {
    if (threadIdx.x == 0) {
        out[off+0] = (float)g_cnt[0] * (1.0f / (float)((size_t)NB*C1*P1*TT));
        out[off+1] = (float)g_cnt[1] * (1.0f / (float)((size_t)NB*C2*P2*TT));
        out[off+2] = (float)g_cnt[2] * (1.0f / (float)((size_t)NB*C3*P3*TT));
    }
}

extern "C" void kernel_launch(void* const* d_in, const int* in_sizes, int n_in,
                              void* d_out, int out_size) {
    const float* x  = (const float*)d_in[0];
    const float* w1 = (const float*)d_in[1];
    const float* w2 = (const float*)d_in[2];
    const float* w3 = (const float*)d_in[3];
    float* out = (float*)d_out;

    const int smem1a = 2*C0*C1*4;   // 65536
    const int smem1b = 4*C0*C1*4;   // 131072
    const int smem2  = 9*C1*C2*4;   // 73728
    cudaFuncSetAttribute((const void*)k_conv1a,
                         cudaFuncAttributeMaxDynamicSharedMemorySize, smem1a);
    cudaFuncSetAttribute((const void*)k_conv1b,
                         cudaFuncAttributeMaxDynamicSharedMemorySize, smem1b);
    cudaFuncSetAttribute((const void*)k_conv2,
                         cudaFuncAttributeMaxDynamicSharedMemorySize, smem2);

    const int wtot = 9*C0*C1 + 9*C1*C2 + 9*C2*C3;
    k_prep<<<256 + (wtot + 255)/256, 256>>>(x, w1, w2, w3);
    k_conv1a<<<296, 1024, smem1a>>>();
    k_conv1b<<<148, 1024, smem1b>>>();
    k_lif1<<<961, 128>>>();
    k_conv2<<<296, 1024, smem2>>>();
    // two pixels per warp: ceil(NB*P2/2) warps, 8 warps per block
    k_lif2<<<(NB*P2/2 + 7)/8, 256>>>();
    k_conv3<<<(FRAMES*(60*60 + 241) + 255)/256, 256>>>();
    k_lif3out<<<(NB*P3 + 255)/256, 256>>>(out);
    k_final<<<1, 32>>>(out, out_size - 3);
}

// round 13
// speedup vs baseline: 1.5205x; 1.0402x over previous
#include <cuda_runtime.h>
#include <stdint.h>

#define TT 32
#define NB 4
#define FRAMES (TT*NB)

#define C0 128
#define H0 16
#define W0 16
#define C1 64
#define H1 31
#define W1 31
#define C2 32
#define H2 61
#define W2 61
#define C3 2
#define H3 121
#define W3 121

#define P0 (H0*W0)     // 256
#define P1 (H1*W1)     // 961
#define P2 (H2*W2)     // 3721
#define P3 (H3*W3)     // 14641

typedef unsigned long long u64;

// ---- device scratch ----
__device__ uint8_t g_cnt0[FRAMES*P0];
__device__ uint8_t g_lst0[FRAMES*P0*128];
__device__ float   g_w1r[9*C0*C1];                    // [tap][ci][co], x2 scaled
__device__ float   g_w2r[9*C1*C2];
__device__ float   g_w3r[9*C2*C3];
__device__ float   g_z1[(size_t)FRAMES*P1*C1];
__device__ uint8_t g_cnt1[FRAMES*P1];
__device__ uint8_t g_lst1[FRAMES*P1*64];
__device__ float   g_z2[(size_t)FRAMES*P2*C2];
__device__ uint8_t g_cnt2[FRAMES*P2];
__device__ uint8_t g_lst2[FRAMES*P2*32];
__device__ float   g_z3[(size_t)FRAMES*P3*C3];
__device__ int     g_cnt[3];
__device__ int     g_ticket;

#define ADD2(A, W) asm("add.rn.f32x2 %0, %0, %1;" : "+l"(A) : "l"(W))

// ---- merged prep: blocks [0,256) build layer-0 lists; rest rearrange weights ----
__global__ void k_prep(const float* __restrict__ x, const float* __restrict__ w1,
                       const float* __restrict__ w2, const float* __restrict__ w3) {
    if (blockIdx.x >= 256) {
        int idx = (blockIdx.x - 256)*256 + threadIdx.x;
        if (idx < 3) g_cnt[idx] = 0;
        if (idx == 3) g_ticket = 0;
        if (idx < 9*C0*C1) {
            int co = idx & 63;
            int ci = (idx >> 6) & 127;
            int tap = idx >> 13;
            g_w1r[idx] = 2.0f * w1[(ci*C1 + co)*9 + tap];
        } else if (idx < 9*C0*C1 + 9*C1*C2) {
            int i = idx - 9*C0*C1;
            int co = i & 31;
            int ci = (i >> 5) & 63;
            int tap = i >> 11;
            g_w2r[i] = 2.0f * w2[(ci*C2 + co)*9 + tap];
        } else if (idx < 9*C0*C1 + 9*C1*C2 + 9*C2*C3) {
            int i = idx - (9*C0*C1 + 9*C1*C2);
            int co = i & 1;
            int ci = (i >> 1) & 31;
            int tap = i >> 6;
            g_w3r[i] = 2.0f * w3[(ci*C3 + co)*9 + tap];
        }
        return;
    }
    const int lane = threadIdx.x & 31;
    const int gw = blockIdx.x*8 + (threadIdx.x >> 5);   // 2048 warps
    const int half = gw & 1;                             // t in [16*half, 16*half+16)
    const int pp = gw >> 1;                              // 1024 = NB*P0 exact
    const int pix = pp % P0;
    const int n   = pp / P0;
    const uint32_t ltmask = (1u << lane) - 1u;
    uint32_t tmask[4];
    #pragma unroll
    for (int w = 0; w < 4; w++) {
        const float4* xp = (const float4*)(x + (((size_t)n*C0 + w*32 + lane)*P0 + pix)*TT)
                           + half*4;
        uint32_t m = 0;
        #pragma unroll
        for (int q = 0; q < 4; q++) {
            float4 vv = xp[q];
            m |= (vv.x >= 0.5f ? 1u : 0u) << (4*q);
            m |= (vv.y >= 0.5f ? 1u : 0u) << (4*q+1);
            m |= (vv.z >= 0.5f ? 1u : 0u) << (4*q+2);
            m |= (vv.w >= 0.5f ? 1u : 0u) << (4*q+3);
        }
        tmask[w] = m;
    }
    #pragma unroll 1
    for (int tt = 0; tt < 16; tt++) {
        const int t = half*16 + tt;
        const int p = (t*NB + n)*P0 + pix;
        uint8_t* lb = g_lst0 + p*128;
        int off = 0;
        #pragma unroll
        for (int w = 0; w < 4; w++) {
            bool s = (tmask[w] >> tt) & 1u;
            uint32_t bal = __ballot_sync(0xffffffffu, s);
            if (s) lb[off + __popc(bal & ltmask)] = (uint8_t)(w*32 + lane);
            off += __popc(bal);
        }
        if (lane == 0) g_cnt0[p] = (uint8_t)off;
    }
}

#define EV1(I) { u64 w_ = wb[(I)*32]; ADD2(acc, w_); }

// ==== layer 1 conv body (merged list, 64 couts packed in f32x2) ====
template<int PH, int PW>
__device__ __forceinline__ void conv1body(float* sW, int firstBlk, int nblk) {
    constexpr int NKH = PH ? 2 : 1;
    constexpr int NKW = PW ? 2 : 1;
    constexpr int NT = NKH*NKW;
    for (int i = threadIdx.x; i < NT*C0*C1; i += 1024) {
        int ti = i >> 13;
        int r  = i & 8191;
        int kh = PH ? (ti/NKW)*2 : 1;
        int kw = PW ? (ti%NKW)*2 : 1;
        sW[i] = g_w1r[(kh*3+kw)*8192 + r];
    }
    __syncthreads();
    const int lane = threadIdx.x & 31;
    const int warp = threadIdx.x >> 5;
    constexpr int ROWS = PH ? H0-1 : H0;
    constexpr int COLS = PW ? W0-1 : W0;
    const int tasks = FRAMES*ROWS*COLS;
    for (int task = (blockIdx.x - firstBlk)*32 + warp; task < tasks; task += nblk*32) {
        const int ocol = task % COLS;
        const int tmp  = task / COLS;
        const int orow = tmp % ROWS;
        const int tn   = tmp / ROWS;
        const int fb   = tn*P0;
        int po[NT];
        #pragma unroll
        for (int a = 0; a < NKH; a++) {
            const int ih = PH ? (a == 0 ? orow+1 : orow) : orow;
            #pragma unroll
            for (int b = 0; b < NKW; b++) {
                const int iw = PW ? (b == 0 ? ocol+1 : ocol) : ocol;
                po[a*NKW+b] = fb + ih*W0 + iw;
            }
        }
        u64 acc = 0ull;
        #pragma unroll
        for (int ti = 0; ti < NT; ti++) {
            const int p = po[ti];
            const int c = g_cnt0[p];
            const uint8_t* lp = g_lst0 + p*128;
            const u64* wb = (const u64*)(sW + ti*8192) + lane;
            int j = 0;
            for (; j + 8 <= c; j += 8) {
                uint2 q = *(const uint2*)(lp + j);
                EV1((q.x      ) & 0xFF) EV1((q.x >>  8) & 0xFF)
                EV1((q.x >> 16) & 0xFF) EV1((q.x >> 24)       )
                EV1((q.y      ) & 0xFF) EV1((q.y >>  8) & 0xFF)
                EV1((q.y >> 16) & 0xFF) EV1((q.y >> 24)       )
            }
            if (j + 4 <= c) {
                uint32_t q = *(const uint32_t*)(lp + j);
                EV1((q      ) & 0xFF) EV1((q >>  8) & 0xFF)
                EV1((q >> 16) & 0xFF) EV1((q >> 24)       )
                j += 4;
            }
            for (; j < c; j++) EV1(lp[j]);
        }
        const int oh = PH ? 2*orow+1 : 2*orow;
        const int ow = PW ? 2*ocol+1 : 2*ocol;
        *(u64*)(g_z1 + ((size_t)tn*P1 + oh*W1 + ow)*C1 + 2*lane) = acc;
    }
}

__global__ void __launch_bounds__(1024)
k_conv1a() {   // classes ee / eo / oe  (<= 64KB smem, 2 blocks/SM)
    extern __shared__ float sW[];
    const int blk = blockIdx.x;
    if (blk < 62)       conv1body<0,0>(sW, 0,   62);
    else if (blk < 179) conv1body<0,1>(sW, 62,  117);
    else                conv1body<1,0>(sW, 179, 117);
}
__global__ void __launch_bounds__(1024)
k_conv1b() {   // class oo (128KB smem)
    extern __shared__ float sW[];
    conv1body<1,1>(sW, 0, 148);
}

// ==== layer 2 conv: 2x2 output-block gather (proven) ====
#define UA(I) { acc11 += sWl[(I)*32]; }
#define UB(I) { const float* eb_ = sWl + (I)*32; acc10 += eb_[2048];  acc11 += eb_[4096]; }
#define UC(I) { const float* eb_ = sWl + (I)*32; acc01 += eb_[6144];  acc11 += eb_[12288]; }
#define UD(I) { const float* eb_ = sWl + (I)*32; acc00 += eb_[8192];  acc01 += eb_[10240]; \
                acc10 += eb_[14336]; acc11 += eb_[16384]; }
#define UE(I) { acc += wb[(I)*32]; }

#define ELOOP(P, U) { \
    const int c_ = g_cnt1[P]; \
    const uint8_t* lp_ = g_lst1 + (P)*64; \
    int j_ = 0; \
    for (; j_ + 4 <= c_; j_ += 4) { \
        uint32_t q_ = *(const uint32_t*)(lp_ + j_); \
        U((q_      ) & 0xFF) U((q_ >>  8) & 0xFF) \
        U((q_ >> 16) & 0xFF) U((q_ >> 24)       ) \
    } \
    for (; j_ < c_; j_++) U(lp_[j_]) \
}

__global__ void __launch_bounds__(1024)
k_conv2() {
    extern __shared__ float sW[];          // all 9 taps: 73728 B
    for (int i = threadIdx.x; i < 9*C1*C2; i += 1024) sW[i] = g_w2r[i];
    __syncthreads();
    const int lane = threadIdx.x & 31;
    const int warp = threadIdx.x >> 5;
    const float* sWl = sW + lane;
    const int BT  = FRAMES*30*30;
    const int TOT = BT + FRAMES*121;
    for (int task = blockIdx.x*32 + warp; task < TOT; task += gridDim.x*32) {
        if (task < BT) {
            const int j  = task % 30;
            const int i  = (task/30) % 30;
            const int tn = task / 900;
            const int fb = tn*P1;
            const int pA = fb + (i+1)*W1 + (j+1);
            const int pB = fb + (i+1)*W1 + j;
            const int pC = fb + i*W1 + (j+1);
            const int pD = fb + i*W1 + j;
            float acc00 = 0.f, acc01 = 0.f, acc10 = 0.f, acc11 = 0.f;
            ELOOP(pA, UA)
            ELOOP(pB, UB)
            ELOOP(pC, UC)
            ELOOP(pD, UD)
            const size_t zb = ((size_t)tn*P2 + (2*i)*W2 + 2*j)*C2 + lane;
            g_z2[zb]             = acc00;
            g_z2[zb + C2]        = acc01;
            g_z2[zb + W2*C2]     = acc10;
            g_z2[zb + W2*C2+C2]  = acc11;
        } else {
            const int e  = task - BT;
            const int tn = e / 121;
            const int r  = e % 121;
            int oh, ow;
            if (r < 61) { oh = 60; ow = r; } else { oh = r - 61; ow = 60; }
            int khs[2], ihs[2], nh; int kws[2], iws[2], nw;
            if (oh & 1) { khs[0]=0; ihs[0]=(oh+1)>>1; khs[1]=2; ihs[1]=(oh-1)>>1; nh=2; }
            else        { khs[0]=1; ihs[0]=oh>>1; nh=1; }
            if (ow & 1) { kws[0]=0; iws[0]=(ow+1)>>1; kws[1]=2; iws[1]=(ow-1)>>1; nw=2; }
            else        { kws[0]=1; iws[0]=ow>>1; nw=1; }
            const int fb = tn*P1;
            float acc = 0.f;
            for (int a = 0; a < nh; a++)
                for (int b = 0; b < nw; b++) {
                    const int p = fb + ihs[a]*W1 + iws[b];
                    const float* wb = sW + (khs[a]*3 + kws[b])*2048 + lane;
                    ELOOP(p, UE)
                }
            g_z2[((size_t)tn*P2 + oh*W2 + ow)*C2 + lane] = acc;
        }
    }
}

// ---- LIF layer 1: warp per (n,pix); software-pipelined z loads ----
__global__ void k_lif1() {
    const int gw = blockIdx.x*4 + (threadIdx.x >> 5);   // 961 x 4 warps = 3844 exact
    const int lane = threadIdx.x & 31;
    const int pix = gw % P1;
    const int n   = gw / P1;
    const uint32_t ltmask = (1u << lane) - 1u;
    const size_t a0 = ((size_t)n*P1 + pix)*C1 + 2*lane;
    const size_t st = (size_t)NB*P1*C1;
    float cur0=0.f, vol0=0.f, cur1=0.f, vol1=0.f;
    int cnt = 0;
    u64 buf[4];
    #pragma unroll
    for (int q = 0; q < 4; q++) buf[q] = *(const u64*)(g_z1 + a0 + (size_t)q*st);
    #pragma unroll
    for (int tb = 0; tb < 8; tb++) {
        u64 nxt[4];
        if (tb < 7) {
            #pragma unroll
            for (int q = 0; q < 4; q++)
                nxt[q] = *(const u64*)(g_z1 + a0 + (size_t)((tb+1)*4 + q)*st);
        }
        #pragma unroll
        for (int q = 0; q < 4; q++) {
            const int t = tb*4 + q;
            float2 zz = *(float2*)&buf[q];
            cur0 = 0.5f*cur0 + zz.x; vol0 = 0.5f*vol0 + cur0;
            cur1 = 0.5f*cur1 + zz.y; vol1 = 0.5f*vol1 + cur1;
            bool s0 = (vol0 >= 1.0f); vol0 = s0 ? 0.f : vol0;
            bool s1 = (vol1 >= 1.0f); vol1 = s1 ? 0.f : vol1;
            cnt += (s0 ? 1 : 0) + (s1 ? 1 : 0);
            uint32_t b0 = __ballot_sync(0xffffffffu, s0);
            uint32_t b1 = __ballot_sync(0xffffffffu, s1);
            const int p = (t*NB + n)*P1 + pix;
            const int off0 = __popc(b0 & ltmask) + __popc(b1 & ltmask);
            if (s0) g_lst1[p*64 + off0] = (uint8_t)(2*lane);
            if (s1) g_lst1[p*64 + off0 + (s0 ? 1 : 0)] = (uint8_t)(2*lane + 1);
            if (lane == 0) g_cnt1[p] = (uint8_t)(__popc(b0) + __popc(b1));
        }
        if (tb < 7) {
            #pragma unroll
            for (int q = 0; q < 4; q++) buf[q] = nxt[q];
        }
    }
    cnt = __reduce_add_sync(0xffffffffu, cnt);
    if (lane == 0) atomicAdd(&g_cnt[0], cnt);
}

// ---- LIF layer 2: warp covers TWO pixels (half-warp each), pipelined u64 loads ----
__global__ void k_lif2() {
    const int gw = blockIdx.x*(blockDim.x >> 5) + (threadIdx.x >> 5);
    const int lane = threadIdx.x & 31;
    const int half = lane >> 4;
    const int j    = lane & 15;              // channel pair (2j, 2j+1)
    const int pix2 = gw*2 + half;
    if (pix2 >= NB*P2) return;               // NB*P2 even -> warps fully in/out
    const int pix = pix2 % P2;
    const int n   = pix2 / P2;
    const uint32_t hmask  = half ? 0xFFFF0000u : 0x0000FFFFu;
    const uint32_t ltmask = ((1u << lane) - 1u) & hmask;
    const size_t a0 = ((size_t)n*P2 + pix)*C2 + 2*j;
    const size_t st = (size_t)NB*P2*C2;
    float cur0=0.f, vol0=0.f, cur1=0.f, vol1=0.f;
    int cnt = 0;
    u64 buf[4];
    #pragma unroll
    for (int q = 0; q < 4; q++) buf[q] = *(const u64*)(g_z2 + a0 + (size_t)q*st);
    #pragma unroll
    for (int tb = 0; tb < 8; tb++) {
        u64 nxt[4];
        if (tb < 7) {
            #pragma unroll
            for (int q = 0; q < 4; q++)
                nxt[q] = *(const u64*)(g_z2 + a0 + (size_t)((tb+1)*4 + q)*st);
        }
        #pragma unroll
        for (int q = 0; q < 4; q++) {
            const int t = tb*4 + q;
            float2 zz = *(float2*)&buf[q];
            cur0 = 0.5f*cur0 + zz.x; vol0 = 0.5f*vol0 + cur0;
            cur1 = 0.5f*cur1 + zz.y; vol1 = 0.5f*vol1 + cur1;
            bool s0 = (vol0 >= 1.0f); vol0 = s0 ? 0.f : vol0;
            bool s1 = (vol1 >= 1.0f); vol1 = s1 ? 0.f : vol1;
            cnt += (s0 ? 1 : 0) + (s1 ? 1 : 0);
            uint32_t b0 = __ballot_sync(0xffffffffu, s0) & hmask;
            uint32_t b1 = __ballot_sync(0xffffffffu, s1) & hmask;
            const int p = (t*NB + n)*P2 + pix;
            const int off0 = __popc(b0 & ltmask) + __popc(b1 & ltmask);
            if (s0) g_lst2[p*32 + off0] = (uint8_t)(2*j);
            if (s1) g_lst2[p*32 + off0 + (s0 ? 1 : 0)] = (uint8_t)(2*j + 1);
            if (j == 0) g_cnt2[p] = (uint8_t)(__popc(b0) + __popc(b1));
        }
        if (tb < 7) {
            #pragma unroll
            for (int q = 0; q < 4; q++) buf[q] = nxt[q];
        }
    }
    cnt = __reduce_add_sync(0xffffffffu, cnt);
    if (lane == 0) atomicAdd(&g_cnt[1], cnt);
}

// ==== layer 3 conv: 2x2 output-block gather (proven) ====
#define VA(I) { ADD2(a11, sW64[      (I)]); }
#define VB(I) { ADD2(a10, sW64[ 32 + (I)]); ADD2(a11, sW64[ 64 + (I)]); }
#define VC(I) { ADD2(a01, sW64[ 96 + (I)]); ADD2(a11, sW64[192 + (I)]); }
#define VD(I) { ADD2(a00, sW64[128 + (I)]); ADD2(a01, sW64[160 + (I)]); \
                ADD2(a10, sW64[224 + (I)]); ADD2(a11, sW64[256 + (I)]); }
#define VE(I) { u64 w_ = wb[(I)]; ADD2(acc, w_); }

#define ELOOP3(P, U) { \
    const int c_ = g_cnt2[P]; \
    const uint8_t* lp_ = g_lst2 + (P)*32; \
    int j_ = 0; \
    for (; j_ + 4 <= c_; j_ += 4) { \
        uint32_t q_ = *(const uint32_t*)(lp_ + j_); \
        U((q_      ) & 0xFF) U((q_ >>  8) & 0xFF) \
        U((q_ >> 16) & 0xFF) U((q_ >> 24)       ) \
    } \
    for (; j_ < c_; j_++) U(lp_[j_]) \
}

__global__ void k_conv3() {
    __shared__ u64 sW64[9*C2];
    for (int i = threadIdx.x; i < 9*C2*2; i += blockDim.x)
        ((float*)sW64)[i] = g_w3r[i];
    __syncthreads();
    const int task = blockIdx.x*blockDim.x + threadIdx.x;
    const int BT  = FRAMES*60*60;
    const int TOT = BT + FRAMES*241;
    if (task >= TOT) return;
    if (task < BT) {
        const int j  = task % 60;
        const int i  = (task/60) % 60;
        const int tn = task / 3600;
        const int fb = tn*P2;
        const int pA = fb + (i+1)*W2 + (j+1);
        const int pB = fb + (i+1)*W2 + j;
        const int pC = fb + i*W2 + (j+1);
        const int pD = fb + i*W2 + j;
        u64 a00=0ull, a01=0ull, a10=0ull, a11=0ull;
        ELOOP3(pA, VA)
        ELOOP3(pB, VB)
        ELOOP3(pC, VC)
        ELOOP3(pD, VD)
        const size_t zb = ((size_t)tn*P3 + (2*i)*W3 + 2*j)*2;
        *(u64*)(g_z3 + zb)          = a00;
        *(u64*)(g_z3 + zb + 2)      = a01;
        *(u64*)(g_z3 + zb + W3*2)   = a10;
        *(u64*)(g_z3 + zb + W3*2+2) = a11;
    } else {
        const int e  = task - BT;
        const int tn = e / 241;
        const int r  = e % 241;
        int oh, ow;
        if (r < 121) { oh = 120; ow = r; } else { oh = r - 121; ow = 120; }
        int khs[2], ihs[2], nh; int kws[2], iws[2], nw;
        if (oh & 1) { khs[0]=0; ihs[0]=(oh+1)>>1; khs[1]=2; ihs[1]=(oh-1)>>1; nh=2; }
        else        { khs[0]=1; ihs[0]=oh>>1; nh=1; }
        if (ow & 1) { kws[0]=0; iws[0]=(ow+1)>>1; kws[1]=2; iws[1]=(ow-1)>>1; nw=2; }
        else        { kws[0]=1; iws[0]=ow>>1; nw=1; }
        u64 acc = 0ull;
        for (int a = 0; a < nh; a++)
            for (int b = 0; b < nw; b++) {
                const int p = tn*P2 + ihs[a]*W2 + iws[b];
                const u64* wb = sW64 + (khs[a]*3 + kws[b])*C2;
                ELOOP3(p, VE)
            }
        *(u64*)(g_z3 + ((size_t)tn*P3 + oh*W3 + ow)*2) = acc;
    }
}

// ---- final LIF: pipelined loads, bitpacked spikes, ticket-based means ----
__global__ void k_lif3out(float* __restrict__ out, int off) {
    const int idx = blockIdx.x*blockDim.x + threadIdx.x;
    const bool valid = (idx < NB*P3);
    int cnt = 0;
    if (valid) {
        const int pix = idx % P3;
        const int n   = idx / P3;
        const size_t a0 = ((size_t)n*P3 + pix)*C3;
        const size_t st = (size_t)NB*P3*C3;
        float cur0=0.f, vol0=0.f, cur1=0.f, vol1=0.f;
        uint32_t bits0 = 0, bits1 = 0;
        u64 buf[4];
        #pragma unroll
        for (int q = 0; q < 4; q++) buf[q] = *(const u64*)(g_z3 + a0 + (size_t)q*st);
        #pragma unroll
        for (int tb = 0; tb < 8; tb++) {
            u64 nxt[4];
            if (tb < 7) {
                #pragma unroll
                for (int q = 0; q < 4; q++)
                    nxt[q] = *(const u64*)(g_z3 + a0 + (size_t)((tb+1)*4 + q)*st);
            }
            #pragma unroll
            for (int q = 0; q < 4; q++) {
                const int t = tb*4 + q;
                float2 zv = *(float2*)&buf[q];
                cur0 = 0.5f*cur0 + zv.x; vol0 = 0.5f*vol0 + cur0;
                cur1 = 0.5f*cur1 + zv.y; vol1 = 0.5f*vol1 + cur1;
                bool s0 = (vol0 >= 1.0f), s1 = (vol1 >= 1.0f);
                vol0 = s0 ? 0.f : vol0;  vol1 = s1 ? 0.f : vol1;
                bits0 |= (s0 ? 1u : 0u) << t;
                bits1 |= (s1 ? 1u : 0u) << t;
            }
            if (tb < 7) {
                #pragma unroll
                for (int q = 0; q < 4; q++) buf[q] = nxt[q];
            }
        }
        cnt = __popc(bits0) + __popc(bits1);
        float4* op0 = (float4*)(out + (((size_t)n*C3 + 0)*P3 + pix)*TT);
        float4* op1 = (float4*)(out + (((size_t)n*C3 + 1)*P3 + pix)*TT);
        #pragma unroll
        for (int q = 0; q < 8; q++) {
            op0[q] = make_float4((float)((bits0 >> (4*q  )) & 1u),
                                 (float)((bits0 >> (4*q+1)) & 1u),
                                 (float)((bits0 >> (4*q+2)) & 1u),
                                 (float)((bits0 >> (4*q+3)) & 1u));
            op1[q] = make_float4((float)((bits1 >> (4*q  )) & 1u),
                                 (float)((bits1 >> (4*q+1)) & 1u),
                                 (float)((bits1 >> (4*q+2)) & 1u),
                                 (float)((bits1 >> (4*q+3)) & 1u));
        }
    }
    cnt = __reduce_add_sync(0xffffffffu, cnt);
    if ((threadIdx.x & 31) == 0 && cnt) atomicAdd(&g_cnt[2], cnt);
    __syncthreads();
    if (threadIdx.x == 0) {
        __threadfence();
        int tk = atomicAdd(&g_ticket, 1);
        if (tk == gridDim.x - 1) {
            out[off+0] = (float)g_cnt[0] * (1.0f / (float)((size_t)NB*C1*P1*TT));
            out[off+1] = (float)g_cnt[1] * (1.0f / (float)((size_t)NB*C2*P2*TT));
            out[off+2] = (float)g_cnt[2] * (1.0f / (float)((size_t)NB*C3*P3*TT));
        }
    }
}

extern "C" void kernel_launch(void* const* d_in, const int* in_sizes, int n_in,
                              void* d_out, int out_size) {
    const float* x  = (const float*)d_in[0];
    const float* w1 = (const float*)d_in[1];
    const float* w2 = (const float*)d_in[2];
    const float* w3 = (const float*)d_in[3];
    float* out = (float*)d_out;

    const int smem1a = 2*C0*C1*4;   // 65536
    const int smem1b = 4*C0*C1*4;   // 131072
    const int smem2  = 9*C1*C2*4;   // 73728
    cudaFuncSetAttribute((const void*)k_conv1a,
                         cudaFuncAttributeMaxDynamicSharedMemorySize, smem1a);
    cudaFuncSetAttribute((const void*)k_conv1b,
                         cudaFuncAttributeMaxDynamicSharedMemorySize, smem1b);
    cudaFuncSetAttribute((const void*)k_conv2,
                         cudaFuncAttributeMaxDynamicSharedMemorySize, smem2);

    const int wtot = 9*C0*C1 + 9*C1*C2 + 9*C2*C3;
    k_prep<<<256 + (wtot + 255)/256, 256>>>(x, w1, w2, w3);
    k_conv1a<<<296, 1024, smem1a>>>();
    k_conv1b<<<148, 1024, smem1b>>>();
    k_lif1<<<961, 128>>>();
    k_conv2<<<296, 1024, smem2>>>();
    k_lif2<<<(NB*P2/2 + 7)/8, 256>>>();
    k_conv3<<<(FRAMES*(60*60 + 241) + 255)/256, 256>>>();
    k_lif3out<<<(NB*P3 + 255)/256, 256>>>(out, out_size - 3);
}